// round 7
// baseline (speedup 1.0000x reference)
#include <cuda_runtime.h>
#include <cuda_bf16.h>
#include <cstdint>

#define B_SZ 2048
#define O_SZ 4096
#define I_SZ 4096
#define KEXP (3 * I_SZ)          // 12288: A'=[hi|lo|hi], B'=[hi|hi|lo]
#define M_HALF 2048              // I/2
#define HSTR 2056                // padded row stride for H (float2 units)

// ---------------------------------------------------------------------------
// Scratch (device globals: no allocation allowed)
// ---------------------------------------------------------------------------
__device__ float2 g_T [(size_t)4096 * HSTR];          // T[k][p] then reused as H[p][k]
__device__ float2 g_U [(size_t)2049 * 4096];          // U[k][p] after axis-0 ifft
__device__ __nv_bfloat16 g_Ap[(size_t)B_SZ * KEXP];
__device__ __nv_bfloat16 g_Bp[(size_t)O_SZ * KEXP];

// ---------------------------------------------------------------------------
// Helpers
// ---------------------------------------------------------------------------
__device__ __forceinline__ uint32_t smem_u32(const void* p) {
    uint32_t a;
    asm("{ .reg .u64 t; cvta.to.shared.u64 t, %1; cvt.u32.u64 %0, t; }" : "=r"(a) : "l"(p));
    return a;
}
__device__ __forceinline__ uint32_t swz(int row, int kb) {
    return (uint32_t)(row * 128 + (kb ^ ((row & 7) << 4)));
}
#define CP16(dst, src) asm volatile("cp.async.cg.shared.global [%0], [%1], 16;" :: "r"(dst), "l"(src) : "memory")
#define CP_COMMIT()    asm volatile("cp.async.commit_group;" ::: "memory")
#define LDSM_X4(r0, r1, r2, r3, addr) \
    asm volatile("ldmatrix.sync.aligned.m8n8.x4.shared.b16 {%0,%1,%2,%3}, [%4];" \
        : "=r"(r0), "=r"(r1), "=r"(r2), "=r"(r3) : "r"(addr))
#define MMA16816(d, a, b) \
    asm volatile("mma.sync.aligned.m16n8k16.row.col.f32.bf16.bf16.f32 " \
        "{%0,%1,%2,%3}, {%4,%5,%6,%7}, {%8,%9}, {%0,%1,%2,%3};" \
        : "+f"((d)[0]), "+f"((d)[1]), "+f"((d)[2]), "+f"((d)[3]) \
        : "r"((a)[0]), "r"((a)[1]), "r"((a)[2]), "r"((a)[3]), "r"((b)[0]), "r"((b)[1]))

__device__ __forceinline__ float2 cmul(float2 a, float2 b) {
    return make_float2(a.x * b.x - a.y * b.y, a.x * b.y + a.y * b.x);
}
__device__ __forceinline__ float2 cadd(float2 a, float2 b) { return make_float2(a.x + b.x, a.y + b.y); }
__device__ __forceinline__ float2 csub(float2 a, float2 b) { return make_float2(a.x - b.x, a.y - b.y); }
__device__ __forceinline__ float2 rot90(float2 a) { return make_float2(-a.y, a.x); }  // * i

__device__ __forceinline__ float2 twid(const float2* tw, int j) {
    float2 t = tw[j & 1023];
    return (j & 1024) ? rot90(t) : t;
}
__device__ __forceinline__ void build_twiddles(float2* tw) {
    for (int j = threadIdx.x; j < 1024; j += 512) {
        float s, c;
        sincosf(1.5339807878856412e-3f * (float)j, &s, &c);   // 2*pi/4096 * j
        tw[j] = make_float2(c, s);
    }
}

// ---------------------------------------------------------------------------
// In-smem IFFT (sign +), bit-reversed input, natural output, unnormalized.
// Radix-2 stage pairs fused into radix-4 passes. 512 threads.
// ---------------------------------------------------------------------------
template <int LOGN>
__device__ __forceinline__ void ifft_smem(float2* xs, const float2* tw) {
    constexpr int N = 1 << LOGN;
    int s = 1;
    if (LOGN & 1) {
        __syncthreads();
        for (int t = threadIdx.x; t < N / 2; t += 512) {
            int i0 = 2 * t;
            float2 u = xs[i0], v = xs[i0 + 1];
            xs[i0] = cadd(u, v);
            xs[i0 + 1] = csub(u, v);
        }
        s = 2;
    }
#pragma unroll
    for (; s <= LOGN; s += 2) {
        const int h = 1 << (s - 1);
        __syncthreads();
        for (int u = threadIdx.x; u < N / 4; u += 512) {
            int k  = u & (h - 1);
            int i0 = ((u >> (s - 1)) << (s + 1)) + k;
            float2 a = xs[i0], b = xs[i0 + h], c = xs[i0 + 2 * h], d = xs[i0 + 3 * h];
            float2 w1 = twid(tw, k << (12 - s));
            b = cmul(b, w1);
            d = cmul(d, w1);
            float2 t0 = cadd(a, b), t1 = csub(a, b);
            float2 t2 = cadd(c, d), t3 = csub(c, d);
            float2 w2 = twid(tw, k << (11 - s));
            t2 = cmul(t2, w2);
            t3 = rot90(cmul(t3, w2));
            xs[i0]         = cadd(t0, t2);
            xs[i0 + 2 * h] = csub(t0, t2);
            xs[i0 + h]     = cadd(t1, t3);
            xs[i0 + 3 * h] = csub(t1, t3);
        }
    }
    __syncthreads();
}

// ---------------------------------------------------------------------------
// K1: masked transpose  T[k][p] = mask*(wr[p][k] + i*wi[p][k]),  k<=2048
// ---------------------------------------------------------------------------
__global__ void kern_mtrans(const float* __restrict__ wr, const float* __restrict__ wi,
                            const int* __restrict__ zmat) {
    __shared__ float2 tile[32][33];
    const int k0 = blockIdx.y * 32, p0 = blockIdx.x * 32;
    const int tx = threadIdx.x, ty = threadIdx.y;
#pragma unroll
    for (int j = 0; j < 32; j += 8) {
        int p = p0 + ty + j, k = k0 + tx;
        float2 v = make_float2(0.f, 0.f);
        if (k <= M_HALF) {
            size_t idx = (size_t)p * I_SZ + k;
            if (zmat[idx] <= 8388608)
                v = make_float2(wr[idx], wi[idx]);
        }
        tile[ty + j][tx] = v;
    }
    __syncthreads();
#pragma unroll
    for (int j = 0; j < 32; j += 8) {
        int k = k0 + ty + j;
        if (k <= M_HALF)
            g_T[(size_t)k * 4096 + p0 + tx] = tile[tx][ty + j];
    }
}

// ---------------------------------------------------------------------------
// K2: axis-0 IFFT (length 4096) on each of the 2049 columns (stored as rows).
// ---------------------------------------------------------------------------
__global__ __launch_bounds__(512) void kern_fft0() {
    __shared__ float2 xs[4096];
    __shared__ float2 tw[1024];
    const int k = blockIdx.x;
    build_twiddles(tw);
    const float2* row = g_T + (size_t)k * 4096;
    for (int p = threadIdx.x; p < 4096; p += 512)
        xs[__brev((unsigned)p) >> 20] = row[p];
    ifft_smem<12>(xs, tw);
    float2* out = g_U + (size_t)k * 4096;
    for (int p = threadIdx.x; p < 4096; p += 512) out[p] = xs[p];
}

// ---------------------------------------------------------------------------
// K3: transpose back  H[p][k] = U[k][p]
// ---------------------------------------------------------------------------
__global__ void kern_trback() {
    __shared__ float2 tile[32][33];
    const int p0 = blockIdx.x * 32, k0 = blockIdx.y * 32;
    const int tx = threadIdx.x, ty = threadIdx.y;
#pragma unroll
    for (int j = 0; j < 32; j += 8) {
        int k = k0 + ty + j;
        tile[ty + j][tx] = (k <= M_HALF) ? g_U[(size_t)k * 4096 + p0 + tx]
                                         : make_float2(0.f, 0.f);
    }
    __syncthreads();
#pragma unroll
    for (int j = 0; j < 32; j += 8) {
        int k = k0 + tx;
        if (k <= M_HALF)
            g_T[(size_t)(p0 + ty + j) * HSTR + k] = tile[tx][ty + j];
    }
}

// ---------------------------------------------------------------------------
// K4: per row o: half-spectrum irfft (2048-pt IFFT + pack), split bf16,
// write g_Bp[o] = [hi|hi|lo].
// ---------------------------------------------------------------------------
__global__ __launch_bounds__(512) void kern_irfft() {
    __shared__ float2 hbuf[2049];
    __shared__ float2 xs[2048];
    __shared__ float2 tw[1024];
    const int o = blockIdx.x;
    build_twiddles(tw);

    const float2* hrow = g_T + (size_t)o * HSTR;
    for (int k = threadIdx.x; k < 2049; k += 512) hbuf[k] = hrow[k];
    __syncthreads();

    for (int k = threadIdx.x; k < 2048; k += 512) {
        float2 Hk, Ck;
        if (k == 0) {
            Hk = make_float2(hbuf[0].x, 0.f);
            Ck = make_float2(hbuf[M_HALF].x, 0.f);
        } else {
            Hk = hbuf[k];
            float2 c = hbuf[M_HALF - k];
            Ck = make_float2(c.x, -c.y);
        }
        float2 S = cadd(Hk, Ck);
        float2 D = csub(Hk, Ck);
        float2 G = cadd(S, rot90(cmul(D, twid(tw, k))));
        xs[__brev((unsigned)k) >> 21] = G;
    }
    ifft_smem<11>(xs, tw);

    const float s = 1.0f / 16777216.0f;
    __nv_bfloat16* rowB = g_Bp + (size_t)o * KEXP;
    for (int m = threadIdx.x; m < 2048; m += 512) {
        float x0 = xs[m].x * s;
        float x1 = xs[m].y * s;
        __nv_bfloat16 h0 = __float2bfloat16(x0);
        __nv_bfloat16 h1 = __float2bfloat16(x1);
        __nv_bfloat16 l0 = __float2bfloat16(x0 - __bfloat162float(h0));
        __nv_bfloat16 l1 = __float2bfloat16(x1 - __bfloat162float(h1));
        __nv_bfloat162 hp; hp.x = h0; hp.y = h1;
        __nv_bfloat162 lp; lp.x = l0; lp.y = l1;
        *(__nv_bfloat162*)(rowB + 2 * m)            = hp;
        *(__nv_bfloat162*)(rowB + I_SZ + 2 * m)     = hp;
        *(__nv_bfloat162*)(rowB + 2 * I_SZ + 2 * m) = lp;
    }
}

// ---------------------------------------------------------------------------
// convA: data -> A' = [hi | lo | hi]
// ---------------------------------------------------------------------------
__global__ __launch_bounds__(256) void kern_convA(const float* __restrict__ data) {
    size_t idx = (size_t)blockIdx.x * 256 + threadIdx.x;
    float x = data[idx];
    __nv_bfloat16 hi = __float2bfloat16(x);
    __nv_bfloat16 lo = __float2bfloat16(x - __bfloat162float(hi));
    size_t b = idx >> 12, i = idx & 4095;
    __nv_bfloat16* row = g_Ap + b * KEXP;
    row[i]            = hi;
    row[I_SZ + i]     = lo;
    row[2 * I_SZ + i] = hi;
}

// ---------------------------------------------------------------------------
// mma.sync GEMM: CTA 128(M) x 256(N), BK=64, 3-stage cp.async, 8 warps in
// 2(M) x 4(N), warp tile 64x64, single barrier per K-tile, loads issued
// before compute.
// ---------------------------------------------------------------------------
#define GM 128
#define GN 256
#define TILE_K 64
#define STAGES 3
#define A_ST (GM * 128)                   // 16KB
#define B_ST (GN * 128)                   // 32KB
#define STAGE_BYTES (A_ST + B_ST)         // 48KB
#define NT (KEXP / TILE_K)                // 192
#define GEMM_SMEM (STAGES * STAGE_BYTES)  // 144KB

__global__ __launch_bounds__(256) void kern_gemm_mma(const float* __restrict__ bias,
                                                     float* __restrict__ C) {
    extern __shared__ char dsm[];
    const uint32_t smem = smem_u32(dsm);
    const int tid  = threadIdx.x;
    const int wid  = tid >> 5;
    const int lane = tid & 31;
    const int m0   = (wid & 1) * 64;       // warp M origin (0, 64)
    const int n0   = (wid >> 1) * 64;      // warp N origin (0, 64, 128, 192)

    const __nv_bfloat16* gA = g_Ap + (size_t)(blockIdx.y * GM) * KEXP;
    const __nv_bfloat16* gB = g_Bp + (size_t)(blockIdx.x * GN) * KEXP;

    const int crow = tid >> 3;             // 0..31
    const int ccol = tid & 7;              // 0..7

    auto load_tile = [&](int t, int s) {
        const uint32_t sA = smem + s * STAGE_BYTES;
        const uint32_t sB = sA + A_ST;
        const char* srcA = (const char*)(gA + (size_t)t * TILE_K);
        const char* srcB = (const char*)(gB + (size_t)t * TILE_K);
#pragma unroll
        for (int r = 0; r < 4; r++) {      // A: 128 rows
            int row = crow + r * 32;
            CP16(sA + swz(row, ccol * 16), srcA + (size_t)row * (KEXP * 2) + ccol * 16);
        }
#pragma unroll
        for (int r = 0; r < 8; r++) {      // B: 256 rows
            int row = crow + r * 32;
            CP16(sB + swz(row, ccol * 16), srcB + (size_t)row * (KEXP * 2) + ccol * 16);
        }
    };

    float acc[4][8][4];
#pragma unroll
    for (int mt = 0; mt < 4; mt++)
#pragma unroll
        for (int nt = 0; nt < 8; nt++)
#pragma unroll
            for (int j = 0; j < 4; j++) acc[mt][nt][j] = 0.f;

    const int l7 = lane & 7;
    const int a_row = m0 + ((lane >> 3) & 1) * 8 + l7;
    const int a_kb  = ((lane >> 4) & 1) * 16;
    const int b_row = n0 + ((lane >> 4) & 1) * 8 + l7;
    const int b_kb  = ((lane >> 3) & 1) * 16;

    load_tile(0, 0); CP_COMMIT();
    load_tile(1, 1); CP_COMMIT();

    for (int t = 0; t < NT; t++) {
        asm volatile("cp.async.wait_group 1;" ::: "memory");
        __syncthreads();

        // prefetch next tile first: overlaps the entire MMA block below
        const int tn = t + 2;
        if (tn < NT) load_tile(tn, tn % STAGES);
        CP_COMMIT();

        const int s = t % STAGES;
        const uint32_t sA = smem + s * STAGE_BYTES;
        const uint32_t sB = sA + A_ST;

#pragma unroll
        for (int ks = 0; ks < 4; ks++) {
            const int kb = ks * 32;
            uint32_t a[4][4], b[8][2];
#pragma unroll
            for (int mt = 0; mt < 4; mt++) {
                uint32_t addr = sA + swz(a_row + mt * 16, kb + a_kb);
                LDSM_X4(a[mt][0], a[mt][1], a[mt][2], a[mt][3], addr);
            }
#pragma unroll
            for (int bt = 0; bt < 4; bt++) {
                uint32_t addr = sB + swz(b_row + bt * 16, kb + b_kb);
                LDSM_X4(b[2 * bt][0], b[2 * bt][1], b[2 * bt + 1][0], b[2 * bt + 1][1], addr);
            }
#pragma unroll
            for (int mt = 0; mt < 4; mt++)
#pragma unroll
                for (int nt = 0; nt < 8; nt++)
                    MMA16816(acc[mt][nt], a[mt], b[nt]);
        }
    }

    const int gid = lane >> 2;
    const int tig = lane & 3;
#pragma unroll
    for (int mt = 0; mt < 4; mt++) {
        const int row0 = blockIdx.y * GM + m0 + mt * 16 + gid;
#pragma unroll
        for (int nt = 0; nt < 8; nt++) {
            const int col = blockIdx.x * GN + n0 + nt * 8 + 2 * tig;
            float b0 = __ldg(bias + col), b1 = __ldg(bias + col + 1);
            *(float2*)(C + (size_t)row0 * O_SZ + col) =
                make_float2(acc[mt][nt][0] + b0, acc[mt][nt][1] + b1);
            *(float2*)(C + (size_t)(row0 + 8) * O_SZ + col) =
                make_float2(acc[mt][nt][2] + b0, acc[mt][nt][3] + b1);
        }
    }
}

// ---------------------------------------------------------------------------
// Launch
// ---------------------------------------------------------------------------
extern "C" void kernel_launch(void* const* d_in, const int* in_sizes, int n_in,
                              void* d_out, int out_size) {
    const float* data = (const float*)d_in[0];
    const float* wr   = (const float*)d_in[1];
    const float* wi   = (const float*)d_in[2];
    const float* bias = (const float*)d_in[3];
    const int*   zmat = (const int*)d_in[4];
    float*       out  = (float*)d_out;

    cudaFuncSetAttribute(kern_gemm_mma, cudaFuncAttributeMaxDynamicSharedMemorySize, GEMM_SMEM);

    kern_convA<<<(B_SZ * I_SZ) / 256, 256>>>(data);
    kern_mtrans<<<dim3(4096 / 32, 65), dim3(32, 8)>>>(wr, wi, zmat);
    kern_fft0<<<2049, 512>>>();
    kern_trback<<<dim3(4096 / 32, 65), dim3(32, 8)>>>();
    kern_irfft<<<O_SZ, 512>>>();
    kern_gemm_mma<<<dim3(O_SZ / GN, B_SZ / GM), 256, GEMM_SMEM>>>(bias, out);
}

// round 8
// speedup vs baseline: 1.0651x; 1.0651x over previous
#include <cuda_runtime.h>
#include <cuda_bf16.h>
#include <cstdint>

#define B_SZ 2048
#define O_SZ 4096
#define I_SZ 4096
#define KEXP (3 * I_SZ)          // 12288: A'=[hi|lo|hi], B'=[hi|hi|lo]
#define M_HALF 2048              // I/2
#define HSTR 2056                // padded row stride for H (float2 units)

// ---------------------------------------------------------------------------
// Scratch (device globals: no allocation allowed)
// ---------------------------------------------------------------------------
__device__ float2 g_T [(size_t)4096 * HSTR];          // T[k][p] then reused as H[p][k]
__device__ float2 g_U [(size_t)2049 * 4096];          // U[k][p] after axis-0 ifft
__device__ __nv_bfloat16 g_Ap[(size_t)B_SZ * KEXP];
__device__ __nv_bfloat16 g_Bp[(size_t)O_SZ * KEXP];

// ---------------------------------------------------------------------------
// Helpers
// ---------------------------------------------------------------------------
__device__ __forceinline__ uint32_t smem_u32(const void* p) {
    uint32_t a;
    asm("{ .reg .u64 t; cvta.to.shared.u64 t, %1; cvt.u32.u64 %0, t; }" : "=r"(a) : "l"(p));
    return a;
}
__device__ __forceinline__ uint32_t swz(int row, int kb) {
    return (uint32_t)(row * 128 + (kb ^ ((row & 7) << 4)));
}
#define CP16(dst, src) asm volatile("cp.async.cg.shared.global [%0], [%1], 16;" :: "r"(dst), "l"(src) : "memory")
#define CP_COMMIT()    asm volatile("cp.async.commit_group;" ::: "memory")
#define LDSM_X4(r0, r1, r2, r3, addr) \
    asm volatile("ldmatrix.sync.aligned.m8n8.x4.shared.b16 {%0,%1,%2,%3}, [%4];" \
        : "=r"(r0), "=r"(r1), "=r"(r2), "=r"(r3) : "r"(addr))
#define MMA16816(d, a, b) \
    asm volatile("mma.sync.aligned.m16n8k16.row.col.f32.bf16.bf16.f32 " \
        "{%0,%1,%2,%3}, {%4,%5,%6,%7}, {%8,%9}, {%0,%1,%2,%3};" \
        : "+f"((d)[0]), "+f"((d)[1]), "+f"((d)[2]), "+f"((d)[3]) \
        : "r"((a)[0]), "r"((a)[1]), "r"((a)[2]), "r"((a)[3]), "r"((b)[0]), "r"((b)[1]))

__device__ __forceinline__ float2 cmul(float2 a, float2 b) {
    return make_float2(a.x * b.x - a.y * b.y, a.x * b.y + a.y * b.x);
}
__device__ __forceinline__ float2 cadd(float2 a, float2 b) { return make_float2(a.x + b.x, a.y + b.y); }
__device__ __forceinline__ float2 csub(float2 a, float2 b) { return make_float2(a.x - b.x, a.y - b.y); }
__device__ __forceinline__ float2 rot90(float2 a) { return make_float2(-a.y, a.x); }  // * i

__device__ __forceinline__ float2 twid(const float2* tw, int j) {
    float2 t = tw[j & 1023];
    return (j & 1024) ? rot90(t) : t;
}
__device__ __forceinline__ void build_twiddles(float2* tw) {
    for (int j = threadIdx.x; j < 1024; j += 512) {
        float s, c;
        sincosf(1.5339807878856412e-3f * (float)j, &s, &c);   // 2*pi/4096 * j
        tw[j] = make_float2(c, s);
    }
}

// ---------------------------------------------------------------------------
// In-smem IFFT (sign +), bit-reversed input, natural output, unnormalized.
// Radix-2 stage pairs fused into radix-4 passes. 512 threads.
// ---------------------------------------------------------------------------
template <int LOGN>
__device__ __forceinline__ void ifft_smem(float2* xs, const float2* tw) {
    constexpr int N = 1 << LOGN;
    int s = 1;
    if (LOGN & 1) {
        __syncthreads();
        for (int t = threadIdx.x; t < N / 2; t += 512) {
            int i0 = 2 * t;
            float2 u = xs[i0], v = xs[i0 + 1];
            xs[i0] = cadd(u, v);
            xs[i0 + 1] = csub(u, v);
        }
        s = 2;
    }
#pragma unroll
    for (; s <= LOGN; s += 2) {
        const int h = 1 << (s - 1);
        __syncthreads();
        for (int u = threadIdx.x; u < N / 4; u += 512) {
            int k  = u & (h - 1);
            int i0 = ((u >> (s - 1)) << (s + 1)) + k;
            float2 a = xs[i0], b = xs[i0 + h], c = xs[i0 + 2 * h], d = xs[i0 + 3 * h];
            float2 w1 = twid(tw, k << (12 - s));
            b = cmul(b, w1);
            d = cmul(d, w1);
            float2 t0 = cadd(a, b), t1 = csub(a, b);
            float2 t2 = cadd(c, d), t3 = csub(c, d);
            float2 w2 = twid(tw, k << (11 - s));
            t2 = cmul(t2, w2);
            t3 = rot90(cmul(t3, w2));
            xs[i0]         = cadd(t0, t2);
            xs[i0 + 2 * h] = csub(t0, t2);
            xs[i0 + h]     = cadd(t1, t3);
            xs[i0 + 3 * h] = csub(t1, t3);
        }
    }
    __syncthreads();
}

// ---------------------------------------------------------------------------
// K1: masked transpose  T[k][p] = mask*(wr[p][k] + i*wi[p][k]),  k<=2048
// ---------------------------------------------------------------------------
__global__ void kern_mtrans(const float* __restrict__ wr, const float* __restrict__ wi,
                            const int* __restrict__ zmat) {
    __shared__ float2 tile[32][33];
    const int k0 = blockIdx.y * 32, p0 = blockIdx.x * 32;
    const int tx = threadIdx.x, ty = threadIdx.y;
#pragma unroll
    for (int j = 0; j < 32; j += 8) {
        int p = p0 + ty + j, k = k0 + tx;
        float2 v = make_float2(0.f, 0.f);
        if (k <= M_HALF) {
            size_t idx = (size_t)p * I_SZ + k;
            if (zmat[idx] <= 8388608)
                v = make_float2(wr[idx], wi[idx]);
        }
        tile[ty + j][tx] = v;
    }
    __syncthreads();
#pragma unroll
    for (int j = 0; j < 32; j += 8) {
        int k = k0 + ty + j;
        if (k <= M_HALF)
            g_T[(size_t)k * 4096 + p0 + tx] = tile[tx][ty + j];
    }
}

// ---------------------------------------------------------------------------
// K2: axis-0 IFFT (length 4096) on each of the 2049 columns (stored as rows).
// ---------------------------------------------------------------------------
__global__ __launch_bounds__(512) void kern_fft0() {
    __shared__ float2 xs[4096];
    __shared__ float2 tw[1024];
    const int k = blockIdx.x;
    build_twiddles(tw);
    const float2* row = g_T + (size_t)k * 4096;
    for (int p = threadIdx.x; p < 4096; p += 512)
        xs[__brev((unsigned)p) >> 20] = row[p];
    ifft_smem<12>(xs, tw);
    float2* out = g_U + (size_t)k * 4096;
    for (int p = threadIdx.x; p < 4096; p += 512) out[p] = xs[p];
}

// ---------------------------------------------------------------------------
// K3: transpose back  H[p][k] = U[k][p]
// ---------------------------------------------------------------------------
__global__ void kern_trback() {
    __shared__ float2 tile[32][33];
    const int p0 = blockIdx.x * 32, k0 = blockIdx.y * 32;
    const int tx = threadIdx.x, ty = threadIdx.y;
#pragma unroll
    for (int j = 0; j < 32; j += 8) {
        int k = k0 + ty + j;
        tile[ty + j][tx] = (k <= M_HALF) ? g_U[(size_t)k * 4096 + p0 + tx]
                                         : make_float2(0.f, 0.f);
    }
    __syncthreads();
#pragma unroll
    for (int j = 0; j < 32; j += 8) {
        int k = k0 + tx;
        if (k <= M_HALF)
            g_T[(size_t)(p0 + ty + j) * HSTR + k] = tile[tx][ty + j];
    }
}

// ---------------------------------------------------------------------------
// K4: per row o: half-spectrum irfft (2048-pt IFFT + pack), split bf16,
// write g_Bp[o] = [hi|hi|lo].
// ---------------------------------------------------------------------------
__global__ __launch_bounds__(512) void kern_irfft() {
    __shared__ float2 hbuf[2049];
    __shared__ float2 xs[2048];
    __shared__ float2 tw[1024];
    const int o = blockIdx.x;
    build_twiddles(tw);

    const float2* hrow = g_T + (size_t)o * HSTR;
    for (int k = threadIdx.x; k < 2049; k += 512) hbuf[k] = hrow[k];
    __syncthreads();

    for (int k = threadIdx.x; k < 2048; k += 512) {
        float2 Hk, Ck;
        if (k == 0) {
            Hk = make_float2(hbuf[0].x, 0.f);
            Ck = make_float2(hbuf[M_HALF].x, 0.f);
        } else {
            Hk = hbuf[k];
            float2 c = hbuf[M_HALF - k];
            Ck = make_float2(c.x, -c.y);
        }
        float2 S = cadd(Hk, Ck);
        float2 D = csub(Hk, Ck);
        float2 G = cadd(S, rot90(cmul(D, twid(tw, k))));
        xs[__brev((unsigned)k) >> 21] = G;
    }
    ifft_smem<11>(xs, tw);

    const float s = 1.0f / 16777216.0f;
    __nv_bfloat16* rowB = g_Bp + (size_t)o * KEXP;
    for (int m = threadIdx.x; m < 2048; m += 512) {
        float x0 = xs[m].x * s;
        float x1 = xs[m].y * s;
        __nv_bfloat16 h0 = __float2bfloat16(x0);
        __nv_bfloat16 h1 = __float2bfloat16(x1);
        __nv_bfloat16 l0 = __float2bfloat16(x0 - __bfloat162float(h0));
        __nv_bfloat16 l1 = __float2bfloat16(x1 - __bfloat162float(h1));
        __nv_bfloat162 hp; hp.x = h0; hp.y = h1;
        __nv_bfloat162 lp; lp.x = l0; lp.y = l1;
        *(__nv_bfloat162*)(rowB + 2 * m)            = hp;
        *(__nv_bfloat162*)(rowB + I_SZ + 2 * m)     = hp;
        *(__nv_bfloat162*)(rowB + 2 * I_SZ + 2 * m) = lp;
    }
}

// ---------------------------------------------------------------------------
// convA: data -> A' = [hi | lo | hi]
// ---------------------------------------------------------------------------
__global__ __launch_bounds__(256) void kern_convA(const float* __restrict__ data) {
    size_t idx = (size_t)blockIdx.x * 256 + threadIdx.x;
    float x = data[idx];
    __nv_bfloat16 hi = __float2bfloat16(x);
    __nv_bfloat16 lo = __float2bfloat16(x - __bfloat162float(hi));
    size_t b = idx >> 12, i = idx & 4095;
    __nv_bfloat16* row = g_Ap + b * KEXP;
    row[i]            = hi;
    row[I_SZ + i]     = lo;
    row[2 * I_SZ + i] = hi;
}

// ---------------------------------------------------------------------------
// mma.sync GEMM: CTA 128x128, 4 warps (2x2), warp tile 64x64, BK=64,
// 3-stage cp.async (96KB -> 2 CTAs/SM), prefetch-first single barrier.
// ---------------------------------------------------------------------------
#define GM 128
#define GN 128
#define TILE_K 64
#define STAGES 3
#define A_ST (GM * 128)                   // 16KB
#define B_ST (GN * 128)                   // 16KB
#define STAGE_BYTES (A_ST + B_ST)         // 32KB
#define NT (KEXP / TILE_K)                // 192
#define GEMM_SMEM (STAGES * STAGE_BYTES)  // 96KB

__global__ __launch_bounds__(128, 2) void kern_gemm_mma(const float* __restrict__ bias,
                                                        float* __restrict__ C) {
    extern __shared__ char dsm[];
    const uint32_t smem = smem_u32(dsm);
    const int tid  = threadIdx.x;
    const int wid  = tid >> 5;
    const int lane = tid & 31;
    const int m0   = (wid & 1) * 64;       // warp M origin
    const int n0   = (wid >> 1) * 64;      // warp N origin

    const __nv_bfloat16* gA = g_Ap + (size_t)(blockIdx.y * GM) * KEXP;
    const __nv_bfloat16* gB = g_Bp + (size_t)(blockIdx.x * GN) * KEXP;

    const int crow = tid >> 3;             // 0..15
    const int ccol = tid & 7;              // 0..7

    auto load_tile = [&](int t, int s) {
        const uint32_t sA = smem + s * STAGE_BYTES;
        const uint32_t sB = sA + A_ST;
        const char* srcA = (const char*)(gA + (size_t)t * TILE_K);
        const char* srcB = (const char*)(gB + (size_t)t * TILE_K);
#pragma unroll
        for (int r = 0; r < 8; r++) {      // A: 128 rows x 8 chunks, 16 threads/row-group
            int row = crow + r * 16;
            CP16(sA + swz(row, ccol * 16), srcA + (size_t)row * (KEXP * 2) + ccol * 16);
        }
#pragma unroll
        for (int r = 0; r < 8; r++) {      // B: 128 rows
            int row = crow + r * 16;
            CP16(sB + swz(row, ccol * 16), srcB + (size_t)row * (KEXP * 2) + ccol * 16);
        }
    };

    float acc[4][8][4];
#pragma unroll
    for (int mt = 0; mt < 4; mt++)
#pragma unroll
        for (int nt = 0; nt < 8; nt++)
#pragma unroll
            for (int j = 0; j < 4; j++) acc[mt][nt][j] = 0.f;

    const int l7 = lane & 7;
    const int a_row = m0 + ((lane >> 3) & 1) * 8 + l7;
    const int a_kb  = ((lane >> 4) & 1) * 16;
    const int b_row = n0 + ((lane >> 4) & 1) * 8 + l7;
    const int b_kb  = ((lane >> 3) & 1) * 16;

    load_tile(0, 0); CP_COMMIT();
    load_tile(1, 1); CP_COMMIT();

#pragma unroll 1
    for (int t = 0; t < NT; t++) {
        asm volatile("cp.async.wait_group 1;" ::: "memory");
        __syncthreads();

        // prefetch next tile first: overlaps the entire MMA block below
        const int tn = t + 2;
        if (tn < NT) load_tile(tn, tn % STAGES);
        CP_COMMIT();

        const int s = t % STAGES;
        const uint32_t sA = smem + s * STAGE_BYTES;
        const uint32_t sB = sA + A_ST;

#pragma unroll
        for (int ks = 0; ks < 4; ks++) {
            const int kb = ks * 32;
            uint32_t a[4][4], b[8][2];
#pragma unroll
            for (int mt = 0; mt < 4; mt++) {
                uint32_t addr = sA + swz(a_row + mt * 16, kb + a_kb);
                LDSM_X4(a[mt][0], a[mt][1], a[mt][2], a[mt][3], addr);
            }
#pragma unroll
            for (int bt = 0; bt < 4; bt++) {
                uint32_t addr = sB + swz(b_row + bt * 16, kb + b_kb);
                LDSM_X4(b[2 * bt][0], b[2 * bt][1], b[2 * bt + 1][0], b[2 * bt + 1][1], addr);
            }
#pragma unroll
            for (int mt = 0; mt < 4; mt++)
#pragma unroll
                for (int nt = 0; nt < 8; nt++)
                    MMA16816(acc[mt][nt], a[mt], b[nt]);
        }
    }

    // epilogue: hoisted bias + store
    const int gid = lane >> 2;
    const int tig = lane & 3;
    float bv[8][2];
#pragma unroll
    for (int nt = 0; nt < 8; nt++) {
        const int col = blockIdx.x * GN + n0 + nt * 8 + 2 * tig;
        bv[nt][0] = __ldg(bias + col);
        bv[nt][1] = __ldg(bias + col + 1);
    }
#pragma unroll
    for (int mt = 0; mt < 4; mt++) {
        const int row0 = blockIdx.y * GM + m0 + mt * 16 + gid;
#pragma unroll
        for (int nt = 0; nt < 8; nt++) {
            const int col = blockIdx.x * GN + n0 + nt * 8 + 2 * tig;
            *(float2*)(C + (size_t)row0 * O_SZ + col) =
                make_float2(acc[mt][nt][0] + bv[nt][0], acc[mt][nt][1] + bv[nt][1]);
            *(float2*)(C + (size_t)(row0 + 8) * O_SZ + col) =
                make_float2(acc[mt][nt][2] + bv[nt][0], acc[mt][nt][3] + bv[nt][1]);
        }
    }
}

// ---------------------------------------------------------------------------
// Launch
// ---------------------------------------------------------------------------
extern "C" void kernel_launch(void* const* d_in, const int* in_sizes, int n_in,
                              void* d_out, int out_size) {
    const float* data = (const float*)d_in[0];
    const float* wr   = (const float*)d_in[1];
    const float* wi   = (const float*)d_in[2];
    const float* bias = (const float*)d_in[3];
    const int*   zmat = (const int*)d_in[4];
    float*       out  = (float*)d_out;

    cudaFuncSetAttribute(kern_gemm_mma, cudaFuncAttributeMaxDynamicSharedMemorySize, GEMM_SMEM);

    kern_convA<<<(B_SZ * I_SZ) / 256, 256>>>(data);
    kern_mtrans<<<dim3(4096 / 32, 65), dim3(32, 8)>>>(wr, wi, zmat);
    kern_fft0<<<2049, 512>>>();
    kern_trback<<<dim3(4096 / 32, 65), dim3(32, 8)>>>();
    kern_irfft<<<O_SZ, 512>>>();
    kern_gemm_mma<<<dim3(O_SZ / GN, B_SZ / GM), 128, GEMM_SMEM>>>(bias, out);
}

// round 9
// speedup vs baseline: 1.2987x; 1.2193x over previous
#include <cuda_runtime.h>
#include <cuda_fp16.h>
#include <cstdint>

#define B_SZ 2048
#define O_SZ 4096
#define I_SZ 4096
#define KEXP (2 * I_SZ)          // 8192: A'=[a|a] fp16, B'=[hi|lo] fp16
#define M_HALF 2048              // I/2
#define HSTR 2056                // padded row stride for H (float2 units)

// ---------------------------------------------------------------------------
// Scratch (device globals: no allocation allowed)
// ---------------------------------------------------------------------------
__device__ float2 g_T [(size_t)4096 * HSTR];          // T[k][p] then reused as H[p][k]
__device__ float2 g_U [(size_t)2049 * 4096];          // U[k][p] after axis-0 ifft
__device__ __half g_Ap[(size_t)B_SZ * KEXP];
__device__ __half g_Bp[(size_t)O_SZ * KEXP];

// ---------------------------------------------------------------------------
// Helpers
// ---------------------------------------------------------------------------
__device__ __forceinline__ uint32_t smem_u32(const void* p) {
    uint32_t a;
    asm("{ .reg .u64 t; cvta.to.shared.u64 t, %1; cvt.u32.u64 %0, t; }" : "=r"(a) : "l"(p));
    return a;
}
__device__ __forceinline__ uint32_t swz(int row, int kb) {
    return (uint32_t)(row * 128 + (kb ^ ((row & 7) << 4)));
}
#define CP16(dst, src) asm volatile("cp.async.cg.shared.global [%0], [%1], 16;" :: "r"(dst), "l"(src) : "memory")
#define CP_COMMIT()    asm volatile("cp.async.commit_group;" ::: "memory")
#define LDSM_X4(r0, r1, r2, r3, addr) \
    asm volatile("ldmatrix.sync.aligned.m8n8.x4.shared.b16 {%0,%1,%2,%3}, [%4];" \
        : "=r"(r0), "=r"(r1), "=r"(r2), "=r"(r3) : "r"(addr))
#define MMA16816(d, a, b) \
    asm volatile("mma.sync.aligned.m16n8k16.row.col.f32.f16.f16.f32 " \
        "{%0,%1,%2,%3}, {%4,%5,%6,%7}, {%8,%9}, {%0,%1,%2,%3};" \
        : "+f"((d)[0]), "+f"((d)[1]), "+f"((d)[2]), "+f"((d)[3]) \
        : "r"((a)[0]), "r"((a)[1]), "r"((a)[2]), "r"((a)[3]), "r"((b)[0]), "r"((b)[1]))

__device__ __forceinline__ float2 cmul(float2 a, float2 b) {
    return make_float2(a.x * b.x - a.y * b.y, a.x * b.y + a.y * b.x);
}
__device__ __forceinline__ float2 cadd(float2 a, float2 b) { return make_float2(a.x + b.x, a.y + b.y); }
__device__ __forceinline__ float2 csub(float2 a, float2 b) { return make_float2(a.x - b.x, a.y - b.y); }
__device__ __forceinline__ float2 rot90(float2 a) { return make_float2(-a.y, a.x); }  // * i

__device__ __forceinline__ float2 twid(const float2* tw, int j) {
    float2 t = tw[j & 1023];
    return (j & 1024) ? rot90(t) : t;
}
__device__ __forceinline__ void build_twiddles(float2* tw) {
    for (int j = threadIdx.x; j < 1024; j += 512) {
        float s, c;
        sincosf(1.5339807878856412e-3f * (float)j, &s, &c);   // 2*pi/4096 * j
        tw[j] = make_float2(c, s);
    }
}

// ---------------------------------------------------------------------------
// In-smem IFFT (sign +), bit-reversed input, natural output, unnormalized.
// Radix-2 stage pairs fused into radix-4 passes. 512 threads.
// ---------------------------------------------------------------------------
template <int LOGN>
__device__ __forceinline__ void ifft_smem(float2* xs, const float2* tw) {
    constexpr int N = 1 << LOGN;
    int s = 1;
    if (LOGN & 1) {
        __syncthreads();
        for (int t = threadIdx.x; t < N / 2; t += 512) {
            int i0 = 2 * t;
            float2 u = xs[i0], v = xs[i0 + 1];
            xs[i0] = cadd(u, v);
            xs[i0 + 1] = csub(u, v);
        }
        s = 2;
    }
#pragma unroll
    for (; s <= LOGN; s += 2) {
        const int h = 1 << (s - 1);
        __syncthreads();
        for (int u = threadIdx.x; u < N / 4; u += 512) {
            int k  = u & (h - 1);
            int i0 = ((u >> (s - 1)) << (s + 1)) + k;
            float2 a = xs[i0], b = xs[i0 + h], c = xs[i0 + 2 * h], d = xs[i0 + 3 * h];
            float2 w1 = twid(tw, k << (12 - s));
            b = cmul(b, w1);
            d = cmul(d, w1);
            float2 t0 = cadd(a, b), t1 = csub(a, b);
            float2 t2 = cadd(c, d), t3 = csub(c, d);
            float2 w2 = twid(tw, k << (11 - s));
            t2 = cmul(t2, w2);
            t3 = rot90(cmul(t3, w2));
            xs[i0]         = cadd(t0, t2);
            xs[i0 + 2 * h] = csub(t0, t2);
            xs[i0 + h]     = cadd(t1, t3);
            xs[i0 + 3 * h] = csub(t1, t3);
        }
    }
    __syncthreads();
}

// ---------------------------------------------------------------------------
// K1: masked transpose  T[k][p] = mask*(wr[p][k] + i*wi[p][k]),  k<=2048
// ---------------------------------------------------------------------------
__global__ void kern_mtrans(const float* __restrict__ wr, const float* __restrict__ wi,
                            const int* __restrict__ zmat) {
    __shared__ float2 tile[32][33];
    const int k0 = blockIdx.y * 32, p0 = blockIdx.x * 32;
    const int tx = threadIdx.x, ty = threadIdx.y;
#pragma unroll
    for (int j = 0; j < 32; j += 8) {
        int p = p0 + ty + j, k = k0 + tx;
        float2 v = make_float2(0.f, 0.f);
        if (k <= M_HALF) {
            size_t idx = (size_t)p * I_SZ + k;
            if (zmat[idx] <= 8388608)
                v = make_float2(wr[idx], wi[idx]);
        }
        tile[ty + j][tx] = v;
    }
    __syncthreads();
#pragma unroll
    for (int j = 0; j < 32; j += 8) {
        int k = k0 + ty + j;
        if (k <= M_HALF)
            g_T[(size_t)k * 4096 + p0 + tx] = tile[tx][ty + j];
    }
}

// ---------------------------------------------------------------------------
// K2: axis-0 IFFT (length 4096) on each of the 2049 columns (stored as rows).
// ---------------------------------------------------------------------------
__global__ __launch_bounds__(512) void kern_fft0() {
    __shared__ float2 xs[4096];
    __shared__ float2 tw[1024];
    const int k = blockIdx.x;
    build_twiddles(tw);
    const float2* row = g_T + (size_t)k * 4096;
    for (int p = threadIdx.x; p < 4096; p += 512)
        xs[__brev((unsigned)p) >> 20] = row[p];
    ifft_smem<12>(xs, tw);
    float2* out = g_U + (size_t)k * 4096;
    for (int p = threadIdx.x; p < 4096; p += 512) out[p] = xs[p];
}

// ---------------------------------------------------------------------------
// K3: transpose back  H[p][k] = U[k][p]
// ---------------------------------------------------------------------------
__global__ void kern_trback() {
    __shared__ float2 tile[32][33];
    const int p0 = blockIdx.x * 32, k0 = blockIdx.y * 32;
    const int tx = threadIdx.x, ty = threadIdx.y;
#pragma unroll
    for (int j = 0; j < 32; j += 8) {
        int k = k0 + ty + j;
        tile[ty + j][tx] = (k <= M_HALF) ? g_U[(size_t)k * 4096 + p0 + tx]
                                         : make_float2(0.f, 0.f);
    }
    __syncthreads();
#pragma unroll
    for (int j = 0; j < 32; j += 8) {
        int k = k0 + tx;
        if (k <= M_HALF)
            g_T[(size_t)(p0 + ty + j) * HSTR + k] = tile[tx][ty + j];
    }
}

// ---------------------------------------------------------------------------
// K4: per row o: half-spectrum irfft (2048-pt IFFT + pack), fp16 2-term split,
// write g_Bp[o] = [hi | lo].
// ---------------------------------------------------------------------------
__global__ __launch_bounds__(512) void kern_irfft() {
    __shared__ float2 hbuf[2049];
    __shared__ float2 xs[2048];
    __shared__ float2 tw[1024];
    const int o = blockIdx.x;
    build_twiddles(tw);

    const float2* hrow = g_T + (size_t)o * HSTR;
    for (int k = threadIdx.x; k < 2049; k += 512) hbuf[k] = hrow[k];
    __syncthreads();

    for (int k = threadIdx.x; k < 2048; k += 512) {
        float2 Hk, Ck;
        if (k == 0) {
            Hk = make_float2(hbuf[0].x, 0.f);
            Ck = make_float2(hbuf[M_HALF].x, 0.f);
        } else {
            Hk = hbuf[k];
            float2 c = hbuf[M_HALF - k];
            Ck = make_float2(c.x, -c.y);
        }
        float2 S = cadd(Hk, Ck);
        float2 D = csub(Hk, Ck);
        float2 G = cadd(S, rot90(cmul(D, twid(tw, k))));
        xs[__brev((unsigned)k) >> 21] = G;
    }
    ifft_smem<11>(xs, tw);

    const float s = 1.0f / 16777216.0f;
    __half* rowB = g_Bp + (size_t)o * KEXP;
    for (int m = threadIdx.x; m < 2048; m += 512) {
        float x0 = xs[m].x * s;
        float x1 = xs[m].y * s;
        __half h0 = __float2half(x0);
        __half h1 = __float2half(x1);
        __half l0 = __float2half(x0 - __half2float(h0));
        __half l1 = __float2half(x1 - __half2float(h1));
        __half2 hp; hp.x = h0; hp.y = h1;
        __half2 lp; lp.x = l0; lp.y = l1;
        *(__half2*)(rowB + 2 * m)        = hp;
        *(__half2*)(rowB + I_SZ + 2 * m) = lp;
    }
}

// ---------------------------------------------------------------------------
// convA: data -> A' = [a | a] (fp16, duplicated)
// ---------------------------------------------------------------------------
__global__ __launch_bounds__(256) void kern_convA(const float* __restrict__ data) {
    size_t idx = (size_t)blockIdx.x * 256 + threadIdx.x;
    __half a = __float2half(data[idx]);
    size_t b = idx >> 12, i = idx & 4095;
    __half* row = g_Ap + b * KEXP;
    row[i]        = a;
    row[I_SZ + i] = a;
}

// ---------------------------------------------------------------------------
// mma.sync GEMM: CTA 128x128, 4 warps (2x2), warp tile 64x64, BK=64,
// 3-stage cp.async (96KB -> 2 CTAs/SM), prefetch-first single barrier.
// ---------------------------------------------------------------------------
#define GM 128
#define GN 128
#define TILE_K 64
#define STAGES 3
#define A_ST (GM * 128)                   // 16KB
#define B_ST (GN * 128)                   // 16KB
#define STAGE_BYTES (A_ST + B_ST)         // 32KB
#define NT (KEXP / TILE_K)                // 128
#define GEMM_SMEM (STAGES * STAGE_BYTES)  // 96KB

__global__ __launch_bounds__(128, 2) void kern_gemm_mma(const float* __restrict__ bias,
                                                        float* __restrict__ C) {
    extern __shared__ char dsm[];
    const uint32_t smem = smem_u32(dsm);
    const int tid  = threadIdx.x;
    const int wid  = tid >> 5;
    const int lane = tid & 31;
    const int m0   = (wid & 1) * 64;       // warp M origin
    const int n0   = (wid >> 1) * 64;      // warp N origin

    const __half* gA = g_Ap + (size_t)(blockIdx.y * GM) * KEXP;
    const __half* gB = g_Bp + (size_t)(blockIdx.x * GN) * KEXP;

    const int crow = tid >> 3;             // 0..15
    const int ccol = tid & 7;              // 0..7

    auto load_tile = [&](int t, int s) {
        const uint32_t sA = smem + s * STAGE_BYTES;
        const uint32_t sB = sA + A_ST;
        const char* srcA = (const char*)(gA + (size_t)t * TILE_K);
        const char* srcB = (const char*)(gB + (size_t)t * TILE_K);
#pragma unroll
        for (int r = 0; r < 8; r++) {
            int row = crow + r * 16;
            CP16(sA + swz(row, ccol * 16), srcA + (size_t)row * (KEXP * 2) + ccol * 16);
        }
#pragma unroll
        for (int r = 0; r < 8; r++) {
            int row = crow + r * 16;
            CP16(sB + swz(row, ccol * 16), srcB + (size_t)row * (KEXP * 2) + ccol * 16);
        }
    };

    float acc[4][8][4];
#pragma unroll
    for (int mt = 0; mt < 4; mt++)
#pragma unroll
        for (int nt = 0; nt < 8; nt++)
#pragma unroll
            for (int j = 0; j < 4; j++) acc[mt][nt][j] = 0.f;

    const int l7 = lane & 7;
    const int a_row = m0 + ((lane >> 3) & 1) * 8 + l7;
    const int a_kb  = ((lane >> 4) & 1) * 16;
    const int b_row = n0 + ((lane >> 4) & 1) * 8 + l7;
    const int b_kb  = ((lane >> 3) & 1) * 16;

    load_tile(0, 0); CP_COMMIT();
    load_tile(1, 1); CP_COMMIT();

#pragma unroll 1
    for (int t = 0; t < NT; t++) {
        asm volatile("cp.async.wait_group 1;" ::: "memory");
        __syncthreads();

        const int tn = t + 2;
        if (tn < NT) load_tile(tn, tn % STAGES);
        CP_COMMIT();

        const int s = t % STAGES;
        const uint32_t sA = smem + s * STAGE_BYTES;
        const uint32_t sB = sA + A_ST;

#pragma unroll
        for (int ks = 0; ks < 4; ks++) {
            const int kb = ks * 32;
            uint32_t a[4][4], b[8][2];
#pragma unroll
            for (int mt = 0; mt < 4; mt++) {
                uint32_t addr = sA + swz(a_row + mt * 16, kb + a_kb);
                LDSM_X4(a[mt][0], a[mt][1], a[mt][2], a[mt][3], addr);
            }
#pragma unroll
            for (int bt = 0; bt < 4; bt++) {
                uint32_t addr = sB + swz(b_row + bt * 16, kb + b_kb);
                LDSM_X4(b[2 * bt][0], b[2 * bt][1], b[2 * bt + 1][0], b[2 * bt + 1][1], addr);
            }
#pragma unroll
            for (int mt = 0; mt < 4; mt++)
#pragma unroll
                for (int nt = 0; nt < 8; nt++)
                    MMA16816(acc[mt][nt], a[mt], b[nt]);
        }
    }

    // epilogue: hoisted bias + store
    const int gid = lane >> 2;
    const int tig = lane & 3;
    float bv[8][2];
#pragma unroll
    for (int nt = 0; nt < 8; nt++) {
        const int col = blockIdx.x * GN + n0 + nt * 8 + 2 * tig;
        bv[nt][0] = __ldg(bias + col);
        bv[nt][1] = __ldg(bias + col + 1);
    }
#pragma unroll
    for (int mt = 0; mt < 4; mt++) {
        const int row0 = blockIdx.y * GM + m0 + mt * 16 + gid;
#pragma unroll
        for (int nt = 0; nt < 8; nt++) {
            const int col = blockIdx.x * GN + n0 + nt * 8 + 2 * tig;
            *(float2*)(C + (size_t)row0 * O_SZ + col) =
                make_float2(acc[mt][nt][0] + bv[nt][0], acc[mt][nt][1] + bv[nt][1]);
            *(float2*)(C + (size_t)(row0 + 8) * O_SZ + col) =
                make_float2(acc[mt][nt][2] + bv[nt][0], acc[mt][nt][3] + bv[nt][1]);
        }
    }
}

// ---------------------------------------------------------------------------
// Launch
// ---------------------------------------------------------------------------
extern "C" void kernel_launch(void* const* d_in, const int* in_sizes, int n_in,
                              void* d_out, int out_size) {
    const float* data = (const float*)d_in[0];
    const float* wr   = (const float*)d_in[1];
    const float* wi   = (const float*)d_in[2];
    const float* bias = (const float*)d_in[3];
    const int*   zmat = (const int*)d_in[4];
    float*       out  = (float*)d_out;

    cudaFuncSetAttribute(kern_gemm_mma, cudaFuncAttributeMaxDynamicSharedMemorySize, GEMM_SMEM);

    kern_convA<<<(B_SZ * I_SZ) / 256, 256>>>(data);
    kern_mtrans<<<dim3(4096 / 32, 65), dim3(32, 8)>>>(wr, wi, zmat);
    kern_fft0<<<2049, 512>>>();
    kern_trback<<<dim3(4096 / 32, 65), dim3(32, 8)>>>();
    kern_irfft<<<O_SZ, 512>>>();
    kern_gemm_mma<<<dim3(O_SZ / GN, B_SZ / GM), 128, GEMM_SMEM>>>(bias, out);
}

// round 10
// speedup vs baseline: 1.8203x; 1.4016x over previous
#include <cuda_runtime.h>
#include <cuda_fp16.h>
#include <cstdint>

#define B_SZ 2048
#define O_SZ 4096
#define I_SZ 4096
#define KEXP I_SZ                // 4096: plain fp16 A and B
#define M_HALF 2048              // I/2
#define HSTR 2056                // padded row stride for H (float2 units)

// ---------------------------------------------------------------------------
// Scratch (device globals: no allocation allowed)
// ---------------------------------------------------------------------------
__device__ float2 g_T [(size_t)4096 * HSTR];          // T[k][p] then reused as H[p][k]
__device__ float2 g_U [(size_t)2049 * 4096];          // U[k][p] after axis-0 ifft
__device__ __half g_Ap[(size_t)B_SZ * KEXP];
__device__ __half g_Bp[(size_t)O_SZ * KEXP];

// ---------------------------------------------------------------------------
// Helpers
// ---------------------------------------------------------------------------
__device__ __forceinline__ uint32_t smem_u32(const void* p) {
    uint32_t a;
    asm("{ .reg .u64 t; cvta.to.shared.u64 t, %1; cvt.u32.u64 %0, t; }" : "=r"(a) : "l"(p));
    return a;
}
__device__ __forceinline__ uint32_t swz(int row, int kb) {
    return (uint32_t)(row * 128 + (kb ^ ((row & 7) << 4)));
}
#define CP16(dst, src) asm volatile("cp.async.cg.shared.global [%0], [%1], 16;" :: "r"(dst), "l"(src) : "memory")
#define CP_COMMIT()    asm volatile("cp.async.commit_group;" ::: "memory")
#define LDSM_X4(r0, r1, r2, r3, addr) \
    asm volatile("ldmatrix.sync.aligned.m8n8.x4.shared.b16 {%0,%1,%2,%3}, [%4];" \
        : "=r"(r0), "=r"(r1), "=r"(r2), "=r"(r3) : "r"(addr))
#define MMA16816(d, a, b) \
    asm volatile("mma.sync.aligned.m16n8k16.row.col.f32.f16.f16.f32 " \
        "{%0,%1,%2,%3}, {%4,%5,%6,%7}, {%8,%9}, {%0,%1,%2,%3};" \
        : "+f"((d)[0]), "+f"((d)[1]), "+f"((d)[2]), "+f"((d)[3]) \
        : "r"((a)[0]), "r"((a)[1]), "r"((a)[2]), "r"((a)[3]), "r"((b)[0]), "r"((b)[1]))

__device__ __forceinline__ float2 cmul(float2 a, float2 b) {
    return make_float2(a.x * b.x - a.y * b.y, a.x * b.y + a.y * b.x);
}
__device__ __forceinline__ float2 cadd(float2 a, float2 b) { return make_float2(a.x + b.x, a.y + b.y); }
__device__ __forceinline__ float2 csub(float2 a, float2 b) { return make_float2(a.x - b.x, a.y - b.y); }
__device__ __forceinline__ float2 rot90(float2 a) { return make_float2(-a.y, a.x); }  // * i

__device__ __forceinline__ float2 twid(const float2* tw, int j) {
    float2 t = tw[j & 1023];
    return (j & 1024) ? rot90(t) : t;
}
__device__ __forceinline__ void build_twiddles(float2* tw) {
    for (int j = threadIdx.x; j < 1024; j += 512) {
        float s, c;
        sincosf(1.5339807878856412e-3f * (float)j, &s, &c);   // 2*pi/4096 * j
        tw[j] = make_float2(c, s);
    }
}

// ---------------------------------------------------------------------------
// In-smem IFFT (sign +), bit-reversed input, natural output, unnormalized.
// Radix-2 stage pairs fused into radix-4 passes. 512 threads.
// ---------------------------------------------------------------------------
template <int LOGN>
__device__ __forceinline__ void ifft_smem(float2* xs, const float2* tw) {
    constexpr int N = 1 << LOGN;
    int s = 1;
    if (LOGN & 1) {
        __syncthreads();
        for (int t = threadIdx.x; t < N / 2; t += 512) {
            int i0 = 2 * t;
            float2 u = xs[i0], v = xs[i0 + 1];
            xs[i0] = cadd(u, v);
            xs[i0 + 1] = csub(u, v);
        }
        s = 2;
    }
#pragma unroll
    for (; s <= LOGN; s += 2) {
        const int h = 1 << (s - 1);
        __syncthreads();
        for (int u = threadIdx.x; u < N / 4; u += 512) {
            int k  = u & (h - 1);
            int i0 = ((u >> (s - 1)) << (s + 1)) + k;
            float2 a = xs[i0], b = xs[i0 + h], c = xs[i0 + 2 * h], d = xs[i0 + 3 * h];
            float2 w1 = twid(tw, k << (12 - s));
            b = cmul(b, w1);
            d = cmul(d, w1);
            float2 t0 = cadd(a, b), t1 = csub(a, b);
            float2 t2 = cadd(c, d), t3 = csub(c, d);
            float2 w2 = twid(tw, k << (11 - s));
            t2 = cmul(t2, w2);
            t3 = rot90(cmul(t3, w2));
            xs[i0]         = cadd(t0, t2);
            xs[i0 + 2 * h] = csub(t0, t2);
            xs[i0 + h]     = cadd(t1, t3);
            xs[i0 + 3 * h] = csub(t1, t3);
        }
    }
    __syncthreads();
}

// ---------------------------------------------------------------------------
// K1: masked transpose  T[k][p] = mask*(wr[p][k] + i*wi[p][k]),  k<=2048
// ---------------------------------------------------------------------------
__global__ void kern_mtrans(const float* __restrict__ wr, const float* __restrict__ wi,
                            const int* __restrict__ zmat) {
    __shared__ float2 tile[32][33];
    const int k0 = blockIdx.y * 32, p0 = blockIdx.x * 32;
    const int tx = threadIdx.x, ty = threadIdx.y;
#pragma unroll
    for (int j = 0; j < 32; j += 8) {
        int p = p0 + ty + j, k = k0 + tx;
        float2 v = make_float2(0.f, 0.f);
        if (k <= M_HALF) {
            size_t idx = (size_t)p * I_SZ + k;
            if (zmat[idx] <= 8388608)
                v = make_float2(wr[idx], wi[idx]);
        }
        tile[ty + j][tx] = v;
    }
    __syncthreads();
#pragma unroll
    for (int j = 0; j < 32; j += 8) {
        int k = k0 + ty + j;
        if (k <= M_HALF)
            g_T[(size_t)k * 4096 + p0 + tx] = tile[tx][ty + j];
    }
}

// ---------------------------------------------------------------------------
// K2: axis-0 IFFT (length 4096) on each of the 2049 columns (stored as rows).
// ---------------------------------------------------------------------------
__global__ __launch_bounds__(512) void kern_fft0() {
    __shared__ float2 xs[4096];
    __shared__ float2 tw[1024];
    const int k = blockIdx.x;
    build_twiddles(tw);
    const float2* row = g_T + (size_t)k * 4096;
    for (int p = threadIdx.x; p < 4096; p += 512)
        xs[__brev((unsigned)p) >> 20] = row[p];
    ifft_smem<12>(xs, tw);
    float2* out = g_U + (size_t)k * 4096;
    for (int p = threadIdx.x; p < 4096; p += 512) out[p] = xs[p];
}

// ---------------------------------------------------------------------------
// K3: transpose back  H[p][k] = U[k][p]
// ---------------------------------------------------------------------------
__global__ void kern_trback() {
    __shared__ float2 tile[32][33];
    const int p0 = blockIdx.x * 32, k0 = blockIdx.y * 32;
    const int tx = threadIdx.x, ty = threadIdx.y;
#pragma unroll
    for (int j = 0; j < 32; j += 8) {
        int k = k0 + ty + j;
        tile[ty + j][tx] = (k <= M_HALF) ? g_U[(size_t)k * 4096 + p0 + tx]
                                         : make_float2(0.f, 0.f);
    }
    __syncthreads();
#pragma unroll
    for (int j = 0; j < 32; j += 8) {
        int k = k0 + tx;
        if (k <= M_HALF)
            g_T[(size_t)(p0 + ty + j) * HSTR + k] = tile[tx][ty + j];
    }
}

// ---------------------------------------------------------------------------
// K4: per row o: half-spectrum irfft (2048-pt IFFT + pack), fp16,
// write g_Bp[o].
// ---------------------------------------------------------------------------
__global__ __launch_bounds__(512) void kern_irfft() {
    __shared__ float2 hbuf[2049];
    __shared__ float2 xs[2048];
    __shared__ float2 tw[1024];
    const int o = blockIdx.x;
    build_twiddles(tw);

    const float2* hrow = g_T + (size_t)o * HSTR;
    for (int k = threadIdx.x; k < 2049; k += 512) hbuf[k] = hrow[k];
    __syncthreads();

    for (int k = threadIdx.x; k < 2048; k += 512) {
        float2 Hk, Ck;
        if (k == 0) {
            Hk = make_float2(hbuf[0].x, 0.f);
            Ck = make_float2(hbuf[M_HALF].x, 0.f);
        } else {
            Hk = hbuf[k];
            float2 c = hbuf[M_HALF - k];
            Ck = make_float2(c.x, -c.y);
        }
        float2 S = cadd(Hk, Ck);
        float2 D = csub(Hk, Ck);
        float2 G = cadd(S, rot90(cmul(D, twid(tw, k))));
        xs[__brev((unsigned)k) >> 21] = G;
    }
    ifft_smem<11>(xs, tw);

    const float s = 1.0f / 16777216.0f;
    __half* rowB = g_Bp + (size_t)o * KEXP;
    for (int m = threadIdx.x; m < 2048; m += 512) {
        __half2 hp;
        hp.x = __float2half(xs[m].x * s);
        hp.y = __float2half(xs[m].y * s);
        *(__half2*)(rowB + 2 * m) = hp;
    }
}

// ---------------------------------------------------------------------------
// convA: data -> fp16
// ---------------------------------------------------------------------------
__global__ __launch_bounds__(256) void kern_convA(const float* __restrict__ data) {
    size_t idx = ((size_t)blockIdx.x * 256 + threadIdx.x) * 4;
    float4 x = *(const float4*)(data + idx);
    __half2 h0, h1;
    h0.x = __float2half(x.x); h0.y = __float2half(x.y);
    h1.x = __float2half(x.z); h1.y = __float2half(x.w);
    *(__half2*)(g_Ap + idx)     = h0;
    *(__half2*)(g_Ap + idx + 2) = h1;
}

// ---------------------------------------------------------------------------
// mma.sync GEMM: CTA 128x128, 4 warps (2x2), warp tile 64x64, BK=64,
// 3-stage cp.async (96KB -> 2 CTAs/SM), prefetch-first single barrier.
// ---------------------------------------------------------------------------
#define GM 128
#define GN 128
#define TILE_K 64
#define STAGES 3
#define A_ST (GM * 128)                   // 16KB
#define B_ST (GN * 128)                   // 16KB
#define STAGE_BYTES (A_ST + B_ST)         // 32KB
#define NT (KEXP / TILE_K)                // 64
#define GEMM_SMEM (STAGES * STAGE_BYTES)  // 96KB

__global__ __launch_bounds__(128, 2) void kern_gemm_mma(const float* __restrict__ bias,
                                                        float* __restrict__ C) {
    extern __shared__ char dsm[];
    const uint32_t smem = smem_u32(dsm);
    const int tid  = threadIdx.x;
    const int wid  = tid >> 5;
    const int lane = tid & 31;
    const int m0   = (wid & 1) * 64;       // warp M origin
    const int n0   = (wid >> 1) * 64;      // warp N origin

    const __half* gA = g_Ap + (size_t)(blockIdx.y * GM) * KEXP;
    const __half* gB = g_Bp + (size_t)(blockIdx.x * GN) * KEXP;

    const int crow = tid >> 3;             // 0..15
    const int ccol = tid & 7;              // 0..7

    auto load_tile = [&](int t, int s) {
        const uint32_t sA = smem + s * STAGE_BYTES;
        const uint32_t sB = sA + A_ST;
        const char* srcA = (const char*)(gA + (size_t)t * TILE_K);
        const char* srcB = (const char*)(gB + (size_t)t * TILE_K);
#pragma unroll
        for (int r = 0; r < 8; r++) {
            int row = crow + r * 16;
            CP16(sA + swz(row, ccol * 16), srcA + (size_t)row * (KEXP * 2) + ccol * 16);
        }
#pragma unroll
        for (int r = 0; r < 8; r++) {
            int row = crow + r * 16;
            CP16(sB + swz(row, ccol * 16), srcB + (size_t)row * (KEXP * 2) + ccol * 16);
        }
    };

    float acc[4][8][4];
#pragma unroll
    for (int mt = 0; mt < 4; mt++)
#pragma unroll
        for (int nt = 0; nt < 8; nt++)
#pragma unroll
            for (int j = 0; j < 4; j++) acc[mt][nt][j] = 0.f;

    const int l7 = lane & 7;
    const int a_row = m0 + ((lane >> 3) & 1) * 8 + l7;
    const int a_kb  = ((lane >> 4) & 1) * 16;
    const int b_row = n0 + ((lane >> 4) & 1) * 8 + l7;
    const int b_kb  = ((lane >> 3) & 1) * 16;

    load_tile(0, 0); CP_COMMIT();
    load_tile(1, 1); CP_COMMIT();

#pragma unroll 1
    for (int t = 0; t < NT; t++) {
        asm volatile("cp.async.wait_group 1;" ::: "memory");
        __syncthreads();

        const int tn = t + 2;
        if (tn < NT) load_tile(tn, tn % STAGES);
        CP_COMMIT();

        const int s = t % STAGES;
        const uint32_t sA = smem + s * STAGE_BYTES;
        const uint32_t sB = sA + A_ST;

#pragma unroll
        for (int ks = 0; ks < 4; ks++) {
            const int kb = ks * 32;
            uint32_t a[4][4], b[8][2];
#pragma unroll
            for (int mt = 0; mt < 4; mt++) {
                uint32_t addr = sA + swz(a_row + mt * 16, kb + a_kb);
                LDSM_X4(a[mt][0], a[mt][1], a[mt][2], a[mt][3], addr);
            }
#pragma unroll
            for (int bt = 0; bt < 4; bt++) {
                uint32_t addr = sB + swz(b_row + bt * 16, kb + b_kb);
                LDSM_X4(b[2 * bt][0], b[2 * bt][1], b[2 * bt + 1][0], b[2 * bt + 1][1], addr);
            }
#pragma unroll
            for (int mt = 0; mt < 4; mt++)
#pragma unroll
                for (int nt = 0; nt < 8; nt++)
                    MMA16816(acc[mt][nt], a[mt], b[nt]);
        }
    }

    // epilogue: hoisted bias + store
    const int gid = lane >> 2;
    const int tig = lane & 3;
    float bv[8][2];
#pragma unroll
    for (int nt = 0; nt < 8; nt++) {
        const int col = blockIdx.x * GN + n0 + nt * 8 + 2 * tig;
        bv[nt][0] = __ldg(bias + col);
        bv[nt][1] = __ldg(bias + col + 1);
    }
#pragma unroll
    for (int mt = 0; mt < 4; mt++) {
        const int row0 = blockIdx.y * GM + m0 + mt * 16 + gid;
#pragma unroll
        for (int nt = 0; nt < 8; nt++) {
            const int col = blockIdx.x * GN + n0 + nt * 8 + 2 * tig;
            *(float2*)(C + (size_t)row0 * O_SZ + col) =
                make_float2(acc[mt][nt][0] + bv[nt][0], acc[mt][nt][1] + bv[nt][1]);
            *(float2*)(C + (size_t)(row0 + 8) * O_SZ + col) =
                make_float2(acc[mt][nt][2] + bv[nt][0], acc[mt][nt][3] + bv[nt][1]);
        }
    }
}

// ---------------------------------------------------------------------------
// Launch
// ---------------------------------------------------------------------------
extern "C" void kernel_launch(void* const* d_in, const int* in_sizes, int n_in,
                              void* d_out, int out_size) {
    const float* data = (const float*)d_in[0];
    const float* wr   = (const float*)d_in[1];
    const float* wi   = (const float*)d_in[2];
    const float* bias = (const float*)d_in[3];
    const int*   zmat = (const int*)d_in[4];
    float*       out  = (float*)d_out;

    cudaFuncSetAttribute(kern_gemm_mma, cudaFuncAttributeMaxDynamicSharedMemorySize, GEMM_SMEM);

    kern_convA<<<(B_SZ * I_SZ) / 1024, 256>>>(data);
    kern_mtrans<<<dim3(4096 / 32, 65), dim3(32, 8)>>>(wr, wi, zmat);
    kern_fft0<<<2049, 512>>>();
    kern_trback<<<dim3(4096 / 32, 65), dim3(32, 8)>>>();
    kern_irfft<<<O_SZ, 512>>>();
    kern_gemm_mma<<<dim3(O_SZ / GN, B_SZ / GM), 128, GEMM_SMEM>>>(bias, out);
}

// round 11
// speedup vs baseline: 2.1587x; 1.1859x over previous
#include <cuda_runtime.h>
#include <cuda_fp16.h>
#include <cstdint>

#define B_SZ 2048
#define O_SZ 4096
#define I_SZ 4096
#define KEXP I_SZ                // 4096: plain fp16 A and B
#define M_HALF 2048              // I/2
#define HSTR 2056                // padded row stride for H (float2 units)

// padded smem index: breaks power-of-two stride bank conflicts
#define XPAD(i) ((i) + ((i) >> 4) + ((i) >> 8))

// ---------------------------------------------------------------------------
// Scratch (device globals: no allocation allowed)
// ---------------------------------------------------------------------------
__device__ float2 g_T [(size_t)4096 * HSTR];          // T[k][p] then reused as H[p][k]
__device__ float2 g_U [(size_t)2049 * 4096];          // U[k][p] after axis-0 ifft
__device__ float2 g_TW[4096];                         // stage twiddles: T_s at offset 2^(s-1)
__device__ __half g_Ap[(size_t)B_SZ * KEXP];
__device__ __half g_Bp[(size_t)O_SZ * KEXP];

// ---------------------------------------------------------------------------
// Helpers
// ---------------------------------------------------------------------------
__device__ __forceinline__ uint32_t smem_u32(const void* p) {
    uint32_t a;
    asm("{ .reg .u64 t; cvta.to.shared.u64 t, %1; cvt.u32.u64 %0, t; }" : "=r"(a) : "l"(p));
    return a;
}
__device__ __forceinline__ uint32_t swz(int row, int kb) {
    return (uint32_t)(row * 128 + (kb ^ ((row & 7) << 4)));
}
#define CP16(dst, src) asm volatile("cp.async.cg.shared.global [%0], [%1], 16;" :: "r"(dst), "l"(src) : "memory")
#define CP_COMMIT()    asm volatile("cp.async.commit_group;" ::: "memory")
#define LDSM_X4(r0, r1, r2, r3, addr) \
    asm volatile("ldmatrix.sync.aligned.m8n8.x4.shared.b16 {%0,%1,%2,%3}, [%4];" \
        : "=r"(r0), "=r"(r1), "=r"(r2), "=r"(r3) : "r"(addr))
#define MMA16816(d, a, b) \
    asm volatile("mma.sync.aligned.m16n8k16.row.col.f32.f16.f16.f32 " \
        "{%0,%1,%2,%3}, {%4,%5,%6,%7}, {%8,%9}, {%0,%1,%2,%3};" \
        : "+f"((d)[0]), "+f"((d)[1]), "+f"((d)[2]), "+f"((d)[3]) \
        : "r"((a)[0]), "r"((a)[1]), "r"((a)[2]), "r"((a)[3]), "r"((b)[0]), "r"((b)[1]))

__device__ __forceinline__ float2 cmul(float2 a, float2 b) {
    return make_float2(a.x * b.x - a.y * b.y, a.x * b.y + a.y * b.x);
}
__device__ __forceinline__ float2 cadd(float2 a, float2 b) { return make_float2(a.x + b.x, a.y + b.y); }
__device__ __forceinline__ float2 csub(float2 a, float2 b) { return make_float2(a.x - b.x, a.y - b.y); }
__device__ __forceinline__ float2 rot90(float2 a) { return make_float2(-a.y, a.x); }  // * i

// ---------------------------------------------------------------------------
// Twiddle table init (one-time): g_TW[2^(s-1)+k] = e^{+2*pi*i*k/2^s}
// ---------------------------------------------------------------------------
__global__ void kern_twinit() {
    int idx = blockIdx.x * 256 + threadIdx.x;      // 0..4095
    if (idx == 0) { g_TW[0] = make_float2(1.f, 0.f); return; }
    int sm1 = 31 - __clz(idx);                     // idx in [2^sm1, 2^(sm1+1)) -> table T_{sm1+1}
    int k = idx - (1 << sm1);
    float ang = 6.283185307179586f * (float)k / (float)(1 << (sm1 + 1));
    float sn, cs;
    sincosf(ang, &sn, &cs);
    g_TW[idx] = make_float2(cs, sn);
}

// ---------------------------------------------------------------------------
// In-smem IFFT (sign +), bit-reversed input (padded layout), natural output,
// unnormalized. Radix-4 passes, per-stage conflict-free twiddle tables.
// Stage s: w1 = T_s[k] = tws[h+k], w2 = T_{s+1}[k] = tws[2h+k].
// ---------------------------------------------------------------------------
template <int LOGN>
__device__ __forceinline__ void ifft_smem(float2* xs, const float2* tws) {
    constexpr int N = 1 << LOGN;
    int s = 1;
    if (LOGN & 1) {                                // plain radix-2 stage, w = 1
        __syncthreads();
        for (int t = threadIdx.x; t < N / 2; t += 512) {
            int i0 = XPAD(2 * t), i1 = XPAD(2 * t + 1);
            float2 u = xs[i0], v = xs[i1];
            xs[i0] = cadd(u, v);
            xs[i1] = csub(u, v);
        }
        s = 2;
    }
#pragma unroll
    for (; s <= LOGN; s += 2) {                    // fused stages s, s+1
        const int h = 1 << (s - 1);
        __syncthreads();
        for (int u = threadIdx.x; u < N / 4; u += 512) {
            int k    = u & (h - 1);
            int base = ((u >> (s - 1)) << (s + 1)) + k;
            int ia = XPAD(base), ib = XPAD(base + h);
            int ic = XPAD(base + 2 * h), id = XPAD(base + 3 * h);
            float2 a = xs[ia], b = xs[ib], c = xs[ic], d = xs[id];
            float2 w1 = tws[h + k];                // T_s[k]
            float2 w2 = tws[2 * h + k];            // T_{s+1}[k]
            b = cmul(b, w1);
            d = cmul(d, w1);
            float2 t0 = cadd(a, b), t1 = csub(a, b);
            float2 t2 = cadd(c, d), t3 = csub(c, d);
            t2 = cmul(t2, w2);
            t3 = rot90(cmul(t3, w2));
            xs[ia] = cadd(t0, t2);
            xs[ic] = csub(t0, t2);
            xs[ib] = cadd(t1, t3);
            xs[id] = csub(t1, t3);
        }
    }
    __syncthreads();
}

// ---------------------------------------------------------------------------
// K1: masked transpose  T[k][p] = mask*(wr[p][k] + i*wi[p][k]),  k<=2048
// ---------------------------------------------------------------------------
__global__ void kern_mtrans(const float* __restrict__ wr, const float* __restrict__ wi,
                            const int* __restrict__ zmat) {
    __shared__ float2 tile[32][33];
    const int k0 = blockIdx.y * 32, p0 = blockIdx.x * 32;
    const int tx = threadIdx.x, ty = threadIdx.y;
#pragma unroll
    for (int j = 0; j < 32; j += 8) {
        int p = p0 + ty + j, k = k0 + tx;
        float2 v = make_float2(0.f, 0.f);
        if (k <= M_HALF) {
            size_t idx = (size_t)p * I_SZ + k;
            if (zmat[idx] <= 8388608)
                v = make_float2(wr[idx], wi[idx]);
        }
        tile[ty + j][tx] = v;
    }
    __syncthreads();
#pragma unroll
    for (int j = 0; j < 32; j += 8) {
        int k = k0 + ty + j;
        if (k <= M_HALF)
            g_T[(size_t)k * 4096 + p0 + tx] = tile[tx][ty + j];
    }
}

// ---------------------------------------------------------------------------
// K2: axis-0 IFFT (length 4096) on each of the 2049 columns (stored as rows).
// Dynamic smem: [xs: 4368 f2][tws: 4096 f2]
// ---------------------------------------------------------------------------
#define FFT0_SMEM ((4368 + 4096) * 8)
__global__ __launch_bounds__(512) void kern_fft0() {
    extern __shared__ float2 dyn0[];
    float2* xs  = dyn0;
    float2* tws = dyn0 + 4368;
    const int k = blockIdx.x;

    for (int i = threadIdx.x; i < 4096; i += 512) tws[i] = g_TW[i];

    const float2* row = g_T + (size_t)k * 4096;
    for (int p = threadIdx.x; p < 4096; p += 512)
        xs[XPAD(__brev((unsigned)p) >> 20)] = row[p];
    ifft_smem<12>(xs, tws);
    float2* out = g_U + (size_t)k * 4096;
    for (int p = threadIdx.x; p < 4096; p += 512) out[p] = xs[XPAD(p)];
}

// ---------------------------------------------------------------------------
// K3: transpose back  H[p][k] = U[k][p]
// ---------------------------------------------------------------------------
__global__ void kern_trback() {
    __shared__ float2 tile[32][33];
    const int p0 = blockIdx.x * 32, k0 = blockIdx.y * 32;
    const int tx = threadIdx.x, ty = threadIdx.y;
#pragma unroll
    for (int j = 0; j < 32; j += 8) {
        int k = k0 + ty + j;
        tile[ty + j][tx] = (k <= M_HALF) ? g_U[(size_t)k * 4096 + p0 + tx]
                                         : make_float2(0.f, 0.f);
    }
    __syncthreads();
#pragma unroll
    for (int j = 0; j < 32; j += 8) {
        int k = k0 + tx;
        if (k <= M_HALF)
            g_T[(size_t)(p0 + ty + j) * HSTR + k] = tile[tx][ty + j];
    }
}

// ---------------------------------------------------------------------------
// K4: per row o: half-spectrum irfft (2048-pt IFFT + pack), fp16 out.
// Dynamic smem: [hbuf: 2049][xs: 2184][tws: 4096]
// ---------------------------------------------------------------------------
#define IRFFT_SMEM ((2049 + 2184 + 4096) * 8)
__global__ __launch_bounds__(512) void kern_irfft() {
    extern __shared__ float2 dyn1[];
    float2* hbuf = dyn1;
    float2* xs   = dyn1 + 2049;
    float2* tws  = dyn1 + 2049 + 2184;
    const int o = blockIdx.x;

    for (int i = threadIdx.x; i < 4096; i += 512) tws[i] = g_TW[i];

    const float2* hrow = g_T + (size_t)o * HSTR;
    for (int k = threadIdx.x; k < 2049; k += 512) hbuf[k] = hrow[k];
    __syncthreads();

    for (int k = threadIdx.x; k < 2048; k += 512) {
        float2 Hk, Ck;
        if (k == 0) {
            Hk = make_float2(hbuf[0].x, 0.f);
            Ck = make_float2(hbuf[M_HALF].x, 0.f);
        } else {
            Hk = hbuf[k];
            float2 c = hbuf[M_HALF - k];
            Ck = make_float2(c.x, -c.y);
        }
        float2 S = cadd(Hk, Ck);
        float2 D = csub(Hk, Ck);
        float2 G = cadd(S, rot90(cmul(D, tws[2048 + k])));   // T_12[k] = e^{2pi i k/4096}
        xs[XPAD(__brev((unsigned)k) >> 21)] = G;
    }
    ifft_smem<11>(xs, tws);

    const float s = 1.0f / 16777216.0f;
    __half* rowB = g_Bp + (size_t)o * KEXP;
    for (int m = threadIdx.x; m < 2048; m += 512) {
        float2 v = xs[XPAD(m)];
        __half2 hp;
        hp.x = __float2half(v.x * s);
        hp.y = __float2half(v.y * s);
        *(__half2*)(rowB + 2 * m) = hp;
    }
}

// ---------------------------------------------------------------------------
// convA: data -> fp16
// ---------------------------------------------------------------------------
__global__ __launch_bounds__(256) void kern_convA(const float* __restrict__ data) {
    size_t idx = ((size_t)blockIdx.x * 256 + threadIdx.x) * 4;
    float4 x = *(const float4*)(data + idx);
    __half2 h0, h1;
    h0.x = __float2half(x.x); h0.y = __float2half(x.y);
    h1.x = __float2half(x.z); h1.y = __float2half(x.w);
    *(__half2*)(g_Ap + idx)     = h0;
    *(__half2*)(g_Ap + idx + 2) = h1;
}

// ---------------------------------------------------------------------------
// mma.sync GEMM: CTA 128x128, 4 warps (2x2), warp tile 64x64, BK=64,
// 3-stage cp.async (96KB -> 2 CTAs/SM), prefetch-first single barrier.
// ---------------------------------------------------------------------------
#define GM 128
#define GN 128
#define TILE_K 64
#define STAGES 3
#define A_ST (GM * 128)                   // 16KB
#define B_ST (GN * 128)                   // 16KB
#define STAGE_BYTES (A_ST + B_ST)         // 32KB
#define NT (KEXP / TILE_K)                // 64
#define GEMM_SMEM (STAGES * STAGE_BYTES)  // 96KB

__global__ __launch_bounds__(128, 2) void kern_gemm_mma(const float* __restrict__ bias,
                                                        float* __restrict__ C) {
    extern __shared__ char dsm[];
    const uint32_t smem = smem_u32(dsm);
    const int tid  = threadIdx.x;
    const int wid  = tid >> 5;
    const int lane = tid & 31;
    const int m0   = (wid & 1) * 64;
    const int n0   = (wid >> 1) * 64;

    const __half* gA = g_Ap + (size_t)(blockIdx.y * GM) * KEXP;
    const __half* gB = g_Bp + (size_t)(blockIdx.x * GN) * KEXP;

    const int crow = tid >> 3;
    const int ccol = tid & 7;

    auto load_tile = [&](int t, int s) {
        const uint32_t sA = smem + s * STAGE_BYTES;
        const uint32_t sB = sA + A_ST;
        const char* srcA = (const char*)(gA + (size_t)t * TILE_K);
        const char* srcB = (const char*)(gB + (size_t)t * TILE_K);
#pragma unroll
        for (int r = 0; r < 8; r++) {
            int row = crow + r * 16;
            CP16(sA + swz(row, ccol * 16), srcA + (size_t)row * (KEXP * 2) + ccol * 16);
        }
#pragma unroll
        for (int r = 0; r < 8; r++) {
            int row = crow + r * 16;
            CP16(sB + swz(row, ccol * 16), srcB + (size_t)row * (KEXP * 2) + ccol * 16);
        }
    };

    float acc[4][8][4];
#pragma unroll
    for (int mt = 0; mt < 4; mt++)
#pragma unroll
        for (int nt = 0; nt < 8; nt++)
#pragma unroll
            for (int j = 0; j < 4; j++) acc[mt][nt][j] = 0.f;

    const int l7 = lane & 7;
    const int a_row = m0 + ((lane >> 3) & 1) * 8 + l7;
    const int a_kb  = ((lane >> 4) & 1) * 16;
    const int b_row = n0 + ((lane >> 4) & 1) * 8 + l7;
    const int b_kb  = ((lane >> 3) & 1) * 16;

    load_tile(0, 0); CP_COMMIT();
    load_tile(1, 1); CP_COMMIT();

#pragma unroll 1
    for (int t = 0; t < NT; t++) {
        asm volatile("cp.async.wait_group 1;" ::: "memory");
        __syncthreads();

        const int tn = t + 2;
        if (tn < NT) load_tile(tn, tn % STAGES);
        CP_COMMIT();

        const int s = t % STAGES;
        const uint32_t sA = smem + s * STAGE_BYTES;
        const uint32_t sB = sA + A_ST;

#pragma unroll
        for (int ks = 0; ks < 4; ks++) {
            const int kb = ks * 32;
            uint32_t a[4][4], b[8][2];
#pragma unroll
            for (int mt = 0; mt < 4; mt++) {
                uint32_t addr = sA + swz(a_row + mt * 16, kb + a_kb);
                LDSM_X4(a[mt][0], a[mt][1], a[mt][2], a[mt][3], addr);
            }
#pragma unroll
            for (int bt = 0; bt < 4; bt++) {
                uint32_t addr = sB + swz(b_row + bt * 16, kb + b_kb);
                LDSM_X4(b[2 * bt][0], b[2 * bt][1], b[2 * bt + 1][0], b[2 * bt + 1][1], addr);
            }
#pragma unroll
            for (int mt = 0; mt < 4; mt++)
#pragma unroll
                for (int nt = 0; nt < 8; nt++)
                    MMA16816(acc[mt][nt], a[mt], b[nt]);
        }
    }

    const int gid = lane >> 2;
    const int tig = lane & 3;
    float bv[8][2];
#pragma unroll
    for (int nt = 0; nt < 8; nt++) {
        const int col = blockIdx.x * GN + n0 + nt * 8 + 2 * tig;
        bv[nt][0] = __ldg(bias + col);
        bv[nt][1] = __ldg(bias + col + 1);
    }
#pragma unroll
    for (int mt = 0; mt < 4; mt++) {
        const int row0 = blockIdx.y * GM + m0 + mt * 16 + gid;
#pragma unroll
        for (int nt = 0; nt < 8; nt++) {
            const int col = blockIdx.x * GN + n0 + nt * 8 + 2 * tig;
            *(float2*)(C + (size_t)row0 * O_SZ + col) =
                make_float2(acc[mt][nt][0] + bv[nt][0], acc[mt][nt][1] + bv[nt][1]);
            *(float2*)(C + (size_t)(row0 + 8) * O_SZ + col) =
                make_float2(acc[mt][nt][2] + bv[nt][0], acc[mt][nt][3] + bv[nt][1]);
        }
    }
}

// ---------------------------------------------------------------------------
// Launch
// ---------------------------------------------------------------------------
extern "C" void kernel_launch(void* const* d_in, const int* in_sizes, int n_in,
                              void* d_out, int out_size) {
    const float* data = (const float*)d_in[0];
    const float* wr   = (const float*)d_in[1];
    const float* wi   = (const float*)d_in[2];
    const float* bias = (const float*)d_in[3];
    const int*   zmat = (const int*)d_in[4];
    float*       out  = (float*)d_out;

    cudaFuncSetAttribute(kern_gemm_mma, cudaFuncAttributeMaxDynamicSharedMemorySize, GEMM_SMEM);
    cudaFuncSetAttribute(kern_fft0,     cudaFuncAttributeMaxDynamicSharedMemorySize, FFT0_SMEM);
    cudaFuncSetAttribute(kern_irfft,    cudaFuncAttributeMaxDynamicSharedMemorySize, IRFFT_SMEM);

    kern_twinit<<<16, 256>>>();
    kern_convA<<<(B_SZ * I_SZ) / 1024, 256>>>(data);
    kern_mtrans<<<dim3(4096 / 32, 65), dim3(32, 8)>>>(wr, wi, zmat);
    kern_fft0<<<2049, 512, FFT0_SMEM>>>();
    kern_trback<<<dim3(4096 / 32, 65), dim3(32, 8)>>>();
    kern_irfft<<<O_SZ, 512, IRFFT_SMEM>>>();
    kern_gemm_mma<<<dim3(O_SZ / GN, B_SZ / GM), 128, GEMM_SMEM>>>(bias, out);
}

// round 12
// speedup vs baseline: 2.3406x; 1.0843x over previous
#include <cuda_runtime.h>
#include <cuda_fp16.h>
#include <cstdint>

#define B_SZ 2048
#define O_SZ 4096
#define I_SZ 4096
#define KEXP I_SZ                // 4096: plain fp16 A and B
#define M_HALF 2048              // I/2
#define HSTR 2056                // padded row stride for H (float2 units)

// padded smem index: breaks power-of-two stride bank conflicts
#define XPAD(i) ((i) + ((i) >> 4) + ((i) >> 8))

// ---------------------------------------------------------------------------
// Scratch (device globals: no allocation allowed)
// ---------------------------------------------------------------------------
__device__ float2 g_T [(size_t)4096 * HSTR];          // T[k][p] then reused as H[p][k]
__device__ float2 g_U [(size_t)2049 * 4096];          // U[k][p] after axis-0 ifft
__device__ float2 g_TW[4096];                         // stage twiddles: T_s at offset 2^(s-1)
__device__ __half g_Ap[(size_t)B_SZ * KEXP];
__device__ __half g_Bp[(size_t)O_SZ * KEXP];

// ---------------------------------------------------------------------------
// Helpers
// ---------------------------------------------------------------------------
__device__ __forceinline__ uint32_t smem_u32(const void* p) {
    uint32_t a;
    asm("{ .reg .u64 t; cvta.to.shared.u64 t, %1; cvt.u32.u64 %0, t; }" : "=r"(a) : "l"(p));
    return a;
}
__device__ __forceinline__ uint32_t swz(int row, int kb) {
    return (uint32_t)(row * 128 + (kb ^ ((row & 7) << 4)));
}
#define CP16(dst, src) asm volatile("cp.async.cg.shared.global [%0], [%1], 16;" :: "r"(dst), "l"(src) : "memory")
#define CP_COMMIT()    asm volatile("cp.async.commit_group;" ::: "memory")
#define LDSM_X4(r0, r1, r2, r3, addr) \
    asm volatile("ldmatrix.sync.aligned.m8n8.x4.shared.b16 {%0,%1,%2,%3}, [%4];" \
        : "=r"(r0), "=r"(r1), "=r"(r2), "=r"(r3) : "r"(addr))
#define MMA16816(d, a, b) \
    asm volatile("mma.sync.aligned.m16n8k16.row.col.f32.f16.f16.f32 " \
        "{%0,%1,%2,%3}, {%4,%5,%6,%7}, {%8,%9}, {%0,%1,%2,%3};" \
        : "+f"((d)[0]), "+f"((d)[1]), "+f"((d)[2]), "+f"((d)[3]) \
        : "r"((a)[0]), "r"((a)[1]), "r"((a)[2]), "r"((a)[3]), "r"((b)[0]), "r"((b)[1]))

__device__ __forceinline__ float2 cmul(float2 a, float2 b) {
    return make_float2(a.x * b.x - a.y * b.y, a.x * b.y + a.y * b.x);
}
__device__ __forceinline__ float2 cadd(float2 a, float2 b) { return make_float2(a.x + b.x, a.y + b.y); }
__device__ __forceinline__ float2 csub(float2 a, float2 b) { return make_float2(a.x - b.x, a.y - b.y); }
__device__ __forceinline__ float2 rot90(float2 a) { return make_float2(-a.y, a.x); }  // * i

// ---------------------------------------------------------------------------
// Twiddle table init (one-time): g_TW[2^(s-1)+k] = e^{+2*pi*i*k/2^s}
// ---------------------------------------------------------------------------
__global__ void kern_twinit() {
    int idx = blockIdx.x * 256 + threadIdx.x;      // 0..4095
    if (idx == 0) { g_TW[0] = make_float2(1.f, 0.f); return; }
    int sm1 = 31 - __clz(idx);
    int k = idx - (1 << sm1);
    float ang = 6.283185307179586f * (float)k / (float)(1 << (sm1 + 1));
    float sn, cs;
    sincosf(ang, &sn, &cs);
    g_TW[idx] = make_float2(cs, sn);
}

// ---------------------------------------------------------------------------
// Register radix-8: three DIT stages (sign +) on e[0..7] (storage order,
// element j at stride-h0 position j). Twiddles w1,w2,w3 = T_s[t],T_{s+1}[t],
// T_{s+2}[t]; pass (1,0) for the constant first-3-stages case.
// ---------------------------------------------------------------------------
__device__ __forceinline__ void radix8(float2 e[8], float2 w1, float2 w2, float2 w3) {
    float2 v;
    // stage s: pairs (0,1)(2,3)(4,5)(6,7), twiddle w1
    v = cmul(e[1], w1); float2 a0 = cadd(e[0], v), a1 = csub(e[0], v);
    v = cmul(e[3], w1); float2 a2 = cadd(e[2], v), a3 = csub(e[2], v);
    v = cmul(e[5], w1); float2 a4 = cadd(e[4], v), a5 = csub(e[4], v);
    v = cmul(e[7], w1); float2 a6 = cadd(e[6], v), a7 = csub(e[6], v);
    // stage s+1: pairs (0,2)(4,6) w2; (1,3)(5,7) i*w2
    float2 iw2 = rot90(w2);
    v = cmul(a2, w2);  float2 b0 = cadd(a0, v), b2 = csub(a0, v);
    v = cmul(a3, iw2); float2 b1 = cadd(a1, v), b3 = csub(a1, v);
    v = cmul(a6, w2);  float2 b4 = cadd(a4, v), b6 = csub(a4, v);
    v = cmul(a7, iw2); float2 b5 = cadd(a5, v), b7 = csub(a5, v);
    // stage s+2: pairs (j, j+4), twiddle w3 * {1, u, i, i*u}, u = e^{i*pi/4}
    const float C = 0.70710678118654752f;
    float2 uw3  = cmul(w3, make_float2(C, C));
    float2 iw3  = rot90(w3);
    float2 iuw3 = rot90(uw3);
    v = cmul(b4, w3);   e[0] = cadd(b0, v); e[4] = csub(b0, v);
    v = cmul(b5, uw3);  e[1] = cadd(b1, v); e[5] = csub(b1, v);
    v = cmul(b6, iw3);  e[2] = cadd(b2, v); e[6] = csub(b2, v);
    v = cmul(b7, iuw3); e[3] = cadd(b3, v); e[7] = csub(b3, v);
}

// fused radix-4 smem pass: stages S, S+1 (h = 2^(S-1)), nbf butterflies
template <int S>
__device__ __forceinline__ void fpass(float2* xs, const float2* tws, int tid, int nbf) {
    const int h = 1 << (S - 1);
    for (int u = tid; u < nbf; u += 512) {
        int k    = u & (h - 1);
        int base = ((u >> (S - 1)) << (S + 1)) + k;
        int ia = XPAD(base), ib = XPAD(base + h);
        int ic = XPAD(base + 2 * h), id = XPAD(base + 3 * h);
        float2 a = xs[ia], b = xs[ib], c = xs[ic], d = xs[id];
        float2 w1 = tws[h + k];
        float2 w2 = tws[2 * h + k];
        b = cmul(b, w1);
        d = cmul(d, w1);
        float2 t0 = cadd(a, b), t1 = csub(a, b);
        float2 t2 = cadd(c, d), t3 = csub(c, d);
        t2 = cmul(t2, w2);
        t3 = rot90(cmul(t3, w2));
        xs[ia] = cadd(t0, t2);
        xs[ic] = csub(t0, t2);
        xs[ib] = cadd(t1, t3);
        xs[id] = csub(t1, t3);
    }
}

// ---------------------------------------------------------------------------
// K1: masked transpose  T[k][p] = mask*(wr[p][k] + i*wi[p][k]),  k<=2048
// ---------------------------------------------------------------------------
__global__ void kern_mtrans(const float* __restrict__ wr, const float* __restrict__ wi,
                            const int* __restrict__ zmat) {
    __shared__ float2 tile[32][33];
    const int k0 = blockIdx.y * 32, p0 = blockIdx.x * 32;
    const int tx = threadIdx.x, ty = threadIdx.y;
#pragma unroll
    for (int j = 0; j < 32; j += 8) {
        int p = p0 + ty + j, k = k0 + tx;
        float2 v = make_float2(0.f, 0.f);
        if (k <= M_HALF) {
            size_t idx = (size_t)p * I_SZ + k;
            if (zmat[idx] <= 8388608)
                v = make_float2(wr[idx], wi[idx]);
        }
        tile[ty + j][tx] = v;
    }
    __syncthreads();
#pragma unroll
    for (int j = 0; j < 32; j += 8) {
        int k = k0 + ty + j;
        if (k <= M_HALF)
            g_T[(size_t)k * 4096 + p0 + tx] = tile[tx][ty + j];
    }
}

// ---------------------------------------------------------------------------
// K2: axis-0 IFFT (4096-pt) per column. Register radix-8 ends, 3 fused smem
// passes in the middle. Dynamic smem: [xs: 4368][tws: 4096]
// ---------------------------------------------------------------------------
#define FFT0_SMEM ((4368 + 4096) * 8)
__global__ __launch_bounds__(512) void kern_fft0() {
    extern __shared__ float2 dyn0[];
    float2* xs  = dyn0;
    float2* tws = dyn0 + 4368;
    const int t = threadIdx.x;
    const int col = blockIdx.x;
    const float2 ONE = make_float2(1.f, 0.f);

    for (int i = t; i < 4096; i += 512) tws[i] = g_TW[i];

    // stages 1-3 in registers, loaded directly from global (coalesced per j):
    // storage group g = brev9(t); element j is input position t + 512*brev3(j)
    const float2* row = g_T + (size_t)col * 4096;
    const int g = __brev((unsigned)t) >> 23;   // brev9(t), t < 512
    float2 e[8];
    e[0] = row[t];          e[1] = row[t + 2048];
    e[2] = row[t + 1024];   e[3] = row[t + 3072];
    e[4] = row[t + 512];    e[5] = row[t + 2560];
    e[6] = row[t + 1536];   e[7] = row[t + 3584];
    radix8(e, ONE, ONE, ONE);
#pragma unroll
    for (int j = 0; j < 8; j++) xs[XPAD(8 * g + j)] = e[j];
    __syncthreads();

    fpass<4>(xs, tws, t, 1024);   // stages 4,5  (h=8)
    __syncthreads();
    fpass<6>(xs, tws, t, 1024);   // stages 6,7  (h=32)
    __syncthreads();
    fpass<8>(xs, tws, t, 1024);   // stages 8,9  (h=128)
    __syncthreads();

    // stages 10-12 in registers: element j at storage t + 512*j
    float2 f[8];
#pragma unroll
    for (int j = 0; j < 8; j++) f[j] = xs[XPAD(t + 512 * j)];
    radix8(f, tws[512 + t], tws[1024 + t], tws[2048 + t]);
    float2* out = g_U + (size_t)col * 4096;
#pragma unroll
    for (int j = 0; j < 8; j++) out[t + 512 * j] = f[j];
}

// ---------------------------------------------------------------------------
// K3: transpose back  H[p][k] = U[k][p]
// ---------------------------------------------------------------------------
__global__ void kern_trback() {
    __shared__ float2 tile[32][33];
    const int p0 = blockIdx.x * 32, k0 = blockIdx.y * 32;
    const int tx = threadIdx.x, ty = threadIdx.y;
#pragma unroll
    for (int j = 0; j < 32; j += 8) {
        int k = k0 + ty + j;
        tile[ty + j][tx] = (k <= M_HALF) ? g_U[(size_t)k * 4096 + p0 + tx]
                                         : make_float2(0.f, 0.f);
    }
    __syncthreads();
#pragma unroll
    for (int j = 0; j < 32; j += 8) {
        int k = k0 + tx;
        if (k <= M_HALF)
            g_T[(size_t)(p0 + ty + j) * HSTR + k] = tile[tx][ty + j];
    }
}

// ---------------------------------------------------------------------------
// K4: per row o: half-spectrum irfft (2048-pt IFFT + pack), register radix-8
// ends (t<256 active), fp16 out. smem: [hbuf: 2049][xs: 2184][tws: 4096]
// ---------------------------------------------------------------------------
#define IRFFT_SMEM ((2049 + 2184 + 4096) * 8)
__global__ __launch_bounds__(512) void kern_irfft() {
    extern __shared__ float2 dyn1[];
    float2* hbuf = dyn1;
    float2* xs   = dyn1 + 2049;
    float2* tws  = dyn1 + 2049 + 2184;
    const int t = threadIdx.x;
    const int o = blockIdx.x;
    const float2 ONE = make_float2(1.f, 0.f);

    for (int i = t; i < 4096; i += 512) tws[i] = g_TW[i];
    const float2* hrow = g_T + (size_t)o * HSTR;
    for (int k = t; k < 2049; k += 512) hbuf[k] = hrow[k];
    __syncthreads();

    // pack + stages 1-3 in registers (t < 256):
    // storage group g = brev8(t); element j is packed position t + 256*brev3(j)
    if (t < 256) {
        const int g = __brev((unsigned)t) >> 24;   // brev8(t), t < 256
        const int B3[8] = {0, 4, 2, 6, 1, 5, 3, 7};
        float2 e[8];
#pragma unroll
        for (int j = 0; j < 8; j++) {
            int kk = t + 256 * B3[j];
            float2 Hk, Ck;
            if (kk == 0) {
                Hk = make_float2(hbuf[0].x, 0.f);
                Ck = make_float2(hbuf[M_HALF].x, 0.f);
            } else {
                Hk = hbuf[kk];
                float2 c = hbuf[M_HALF - kk];
                Ck = make_float2(c.x, -c.y);
            }
            float2 S = cadd(Hk, Ck);
            float2 D = csub(Hk, Ck);
            e[j] = cadd(S, rot90(cmul(D, tws[2048 + kk])));   // T_12[kk]
        }
        radix8(e, ONE, ONE, ONE);
#pragma unroll
        for (int j = 0; j < 8; j++) xs[XPAD(8 * g + j)] = e[j];
    }
    __syncthreads();

    fpass<4>(xs, tws, t, 512);    // stages 4,5 (h=8)
    __syncthreads();
    fpass<6>(xs, tws, t, 512);    // stages 6,7 (h=32)
    __syncthreads();
    // single radix-2 stage 8 (h=128)
    for (int u = t; u < 1024; u += 512) {
        int kk = u & 127;
        int i0 = ((u >> 7) << 8) + kk;
        int ia = XPAD(i0), ib = XPAD(i0 + 128);
        float2 w = tws[128 + kk];                 // T_8[kk]
        float2 uu = xs[ia], v = cmul(xs[ib], w);
        xs[ia] = cadd(uu, v);
        xs[ib] = csub(uu, v);
    }
    __syncthreads();

    // stages 9-11 in registers (t < 256): element j at storage t + 256*j
    if (t < 256) {
        float2 f[8];
#pragma unroll
        for (int j = 0; j < 8; j++) f[j] = xs[XPAD(t + 256 * j)];
        radix8(f, tws[256 + t], tws[512 + t], tws[1024 + t]);
        const float s = 1.0f / 16777216.0f;
        __half* rowB = g_Bp + (size_t)o * KEXP;
#pragma unroll
        for (int j = 0; j < 8; j++) {
            int m = t + 256 * j;
            __half2 hp;
            hp.x = __float2half(f[j].x * s);
            hp.y = __float2half(f[j].y * s);
            *(__half2*)(rowB + 2 * m) = hp;
        }
    }
}

// ---------------------------------------------------------------------------
// convA: data -> fp16
// ---------------------------------------------------------------------------
__global__ __launch_bounds__(256) void kern_convA(const float* __restrict__ data) {
    size_t idx = ((size_t)blockIdx.x * 256 + threadIdx.x) * 4;
    float4 x = *(const float4*)(data + idx);
    __half2 h0, h1;
    h0.x = __float2half(x.x); h0.y = __float2half(x.y);
    h1.x = __float2half(x.z); h1.y = __float2half(x.w);
    *(__half2*)(g_Ap + idx)     = h0;
    *(__half2*)(g_Ap + idx + 2) = h1;
}

// ---------------------------------------------------------------------------
// mma.sync GEMM: CTA 128x128, 4 warps (2x2), warp tile 64x64, BK=64,
// 3-stage cp.async (96KB -> 2 CTAs/SM), prefetch-first single barrier.
// ---------------------------------------------------------------------------
#define GM 128
#define GN 128
#define TILE_K 64
#define STAGES 3
#define A_ST (GM * 128)                   // 16KB
#define B_ST (GN * 128)                   // 16KB
#define STAGE_BYTES (A_ST + B_ST)         // 32KB
#define NT (KEXP / TILE_K)                // 64
#define GEMM_SMEM (STAGES * STAGE_BYTES)  // 96KB

__global__ __launch_bounds__(128, 2) void kern_gemm_mma(const float* __restrict__ bias,
                                                        float* __restrict__ C) {
    extern __shared__ char dsm[];
    const uint32_t smem = smem_u32(dsm);
    const int tid  = threadIdx.x;
    const int wid  = tid >> 5;
    const int lane = tid & 31;
    const int m0   = (wid & 1) * 64;
    const int n0   = (wid >> 1) * 64;

    const __half* gA = g_Ap + (size_t)(blockIdx.y * GM) * KEXP;
    const __half* gB = g_Bp + (size_t)(blockIdx.x * GN) * KEXP;

    const int crow = tid >> 3;
    const int ccol = tid & 7;

    auto load_tile = [&](int t, int s) {
        const uint32_t sA = smem + s * STAGE_BYTES;
        const uint32_t sB = sA + A_ST;
        const char* srcA = (const char*)(gA + (size_t)t * TILE_K);
        const char* srcB = (const char*)(gB + (size_t)t * TILE_K);
#pragma unroll
        for (int r = 0; r < 8; r++) {
            int row = crow + r * 16;
            CP16(sA + swz(row, ccol * 16), srcA + (size_t)row * (KEXP * 2) + ccol * 16);
        }
#pragma unroll
        for (int r = 0; r < 8; r++) {
            int row = crow + r * 16;
            CP16(sB + swz(row, ccol * 16), srcB + (size_t)row * (KEXP * 2) + ccol * 16);
        }
    };

    float acc[4][8][4];
#pragma unroll
    for (int mt = 0; mt < 4; mt++)
#pragma unroll
        for (int nt = 0; nt < 8; nt++)
#pragma unroll
            for (int j = 0; j < 4; j++) acc[mt][nt][j] = 0.f;

    const int l7 = lane & 7;
    const int a_row = m0 + ((lane >> 3) & 1) * 8 + l7;
    const int a_kb  = ((lane >> 4) & 1) * 16;
    const int b_row = n0 + ((lane >> 4) & 1) * 8 + l7;
    const int b_kb  = ((lane >> 3) & 1) * 16;

    load_tile(0, 0); CP_COMMIT();
    load_tile(1, 1); CP_COMMIT();

#pragma unroll 1
    for (int t = 0; t < NT; t++) {
        asm volatile("cp.async.wait_group 1;" ::: "memory");
        __syncthreads();

        const int tn = t + 2;
        if (tn < NT) load_tile(tn, tn % STAGES);
        CP_COMMIT();

        const int s = t % STAGES;
        const uint32_t sA = smem + s * STAGE_BYTES;
        const uint32_t sB = sA + A_ST;

#pragma unroll
        for (int ks = 0; ks < 4; ks++) {
            const int kb = ks * 32;
            uint32_t a[4][4], b[8][2];
#pragma unroll
            for (int mt = 0; mt < 4; mt++) {
                uint32_t addr = sA + swz(a_row + mt * 16, kb + a_kb);
                LDSM_X4(a[mt][0], a[mt][1], a[mt][2], a[mt][3], addr);
            }
#pragma unroll
            for (int bt = 0; bt < 4; bt++) {
                uint32_t addr = sB + swz(b_row + bt * 16, kb + b_kb);
                LDSM_X4(b[2 * bt][0], b[2 * bt][1], b[2 * bt + 1][0], b[2 * bt + 1][1], addr);
            }
#pragma unroll
            for (int mt = 0; mt < 4; mt++)
#pragma unroll
                for (int nt = 0; nt < 8; nt++)
                    MMA16816(acc[mt][nt], a[mt], b[nt]);
        }
    }

    const int gid = lane >> 2;
    const int tig = lane & 3;
    float bv[8][2];
#pragma unroll
    for (int nt = 0; nt < 8; nt++) {
        const int col = blockIdx.x * GN + n0 + nt * 8 + 2 * tig;
        bv[nt][0] = __ldg(bias + col);
        bv[nt][1] = __ldg(bias + col + 1);
    }
#pragma unroll
    for (int mt = 0; mt < 4; mt++) {
        const int row0 = blockIdx.y * GM + m0 + mt * 16 + gid;
#pragma unroll
        for (int nt = 0; nt < 8; nt++) {
            const int col = blockIdx.x * GN + n0 + nt * 8 + 2 * tig;
            *(float2*)(C + (size_t)row0 * O_SZ + col) =
                make_float2(acc[mt][nt][0] + bv[nt][0], acc[mt][nt][1] + bv[nt][1]);
            *(float2*)(C + (size_t)(row0 + 8) * O_SZ + col) =
                make_float2(acc[mt][nt][2] + bv[nt][0], acc[mt][nt][3] + bv[nt][1]);
        }
    }
}

// ---------------------------------------------------------------------------
// Launch
// ---------------------------------------------------------------------------
extern "C" void kernel_launch(void* const* d_in, const int* in_sizes, int n_in,
                              void* d_out, int out_size) {
    const float* data = (const float*)d_in[0];
    const float* wr   = (const float*)d_in[1];
    const float* wi   = (const float*)d_in[2];
    const float* bias = (const float*)d_in[3];
    const int*   zmat = (const int*)d_in[4];
    float*       out  = (float*)d_out;

    cudaFuncSetAttribute(kern_gemm_mma, cudaFuncAttributeMaxDynamicSharedMemorySize, GEMM_SMEM);
    cudaFuncSetAttribute(kern_fft0,     cudaFuncAttributeMaxDynamicSharedMemorySize, FFT0_SMEM);
    cudaFuncSetAttribute(kern_irfft,    cudaFuncAttributeMaxDynamicSharedMemorySize, IRFFT_SMEM);

    kern_twinit<<<16, 256>>>();
    kern_convA<<<(B_SZ * I_SZ) / 1024, 256>>>(data);
    kern_mtrans<<<dim3(4096 / 32, 65), dim3(32, 8)>>>(wr, wi, zmat);
    kern_fft0<<<2049, 512, FFT0_SMEM>>>();
    kern_trback<<<dim3(4096 / 32, 65), dim3(32, 8)>>>();
    kern_irfft<<<O_SZ, 512, IRFFT_SMEM>>>();
    kern_gemm_mma<<<dim3(O_SZ / GN, B_SZ / GM), 128, GEMM_SMEM>>>(bias, out);
}

// round 13
// speedup vs baseline: 2.6119x; 1.1159x over previous
#include <cuda_runtime.h>
#include <cuda_fp16.h>
#include <cstdint>

#define B_SZ 2048
#define O_SZ 4096
#define I_SZ 4096
#define KEXP I_SZ                // 4096: plain fp16 A and B
#define M_HALF 2048              // I/2
#define HSTR 2056                // padded row stride for H (float2 units)

// padded smem index: breaks power-of-two stride bank conflicts
#define XPAD(i) ((i) + ((i) >> 4) + ((i) >> 8))

// ---------------------------------------------------------------------------
// Scratch (device globals: no allocation allowed)
// ---------------------------------------------------------------------------
__device__ float2 g_T [(size_t)4096 * HSTR];          // T[k][p] then reused as H[p][k]
__device__ float2 g_U [(size_t)2049 * 4096];          // U[k][p] after axis-0 ifft
__device__ float2 g_TW[4096];                         // stage twiddles: T_s at offset 2^(s-1)
__device__ __half g_Ap[(size_t)B_SZ * KEXP];
__device__ __half g_Bp[(size_t)O_SZ * KEXP];

// ---------------------------------------------------------------------------
// Helpers
// ---------------------------------------------------------------------------
__device__ __forceinline__ uint32_t smem_u32(const void* p) {
    uint32_t a;
    asm("{ .reg .u64 t; cvta.to.shared.u64 t, %1; cvt.u32.u64 %0, t; }" : "=r"(a) : "l"(p));
    return a;
}
__device__ __forceinline__ uint32_t swz(int row, int kb) {
    return (uint32_t)(row * 128 + (kb ^ ((row & 7) << 4)));
}
#define CP16(dst, src) asm volatile("cp.async.cg.shared.global [%0], [%1], 16;" :: "r"(dst), "l"(src) : "memory")
#define CP_COMMIT()    asm volatile("cp.async.commit_group;" ::: "memory")
#define LDSM_X4(r0, r1, r2, r3, addr) \
    asm volatile("ldmatrix.sync.aligned.m8n8.x4.shared.b16 {%0,%1,%2,%3}, [%4];" \
        : "=r"(r0), "=r"(r1), "=r"(r2), "=r"(r3) : "r"(addr))
#define MMA16816(d, a, b) \
    asm volatile("mma.sync.aligned.m16n8k16.row.col.f32.f16.f16.f32 " \
        "{%0,%1,%2,%3}, {%4,%5,%6,%7}, {%8,%9}, {%0,%1,%2,%3};" \
        : "+f"((d)[0]), "+f"((d)[1]), "+f"((d)[2]), "+f"((d)[3]) \
        : "r"((a)[0]), "r"((a)[1]), "r"((a)[2]), "r"((a)[3]), "r"((b)[0]), "r"((b)[1]))

__device__ __forceinline__ float2 cmul(float2 a, float2 b) {
    return make_float2(a.x * b.x - a.y * b.y, a.x * b.y + a.y * b.x);
}
__device__ __forceinline__ float2 cadd(float2 a, float2 b) { return make_float2(a.x + b.x, a.y + b.y); }
__device__ __forceinline__ float2 csub(float2 a, float2 b) { return make_float2(a.x - b.x, a.y - b.y); }
__device__ __forceinline__ float2 rot90(float2 a) { return make_float2(-a.y, a.x); }  // * i

__device__ __forceinline__ float2 ldtw(const float2* __restrict__ p) {
    // coalesced global twiddle load (L2-resident table)
    float2 v;
    v.x = __ldg(&p->x);
    v.y = __ldg(&p->y);
    return v;
}

// ---------------------------------------------------------------------------
// Twiddle table init (one-time): g_TW[2^(s-1)+k] = e^{+2*pi*i*k/2^s}
// ---------------------------------------------------------------------------
__global__ void kern_twinit() {
    int idx = blockIdx.x * 256 + threadIdx.x;      // 0..4095
    if (idx == 0) { g_TW[0] = make_float2(1.f, 0.f); return; }
    int sm1 = 31 - __clz(idx);
    int k = idx - (1 << sm1);
    float ang = 6.283185307179586f * (float)k / (float)(1 << (sm1 + 1));
    float sn, cs;
    sincosf(ang, &sn, &cs);
    g_TW[idx] = make_float2(cs, sn);
}

// ---------------------------------------------------------------------------
// Register radix-8: three DIT stages (sign +).
// ---------------------------------------------------------------------------
__device__ __forceinline__ void radix8(float2 e[8], float2 w1, float2 w2, float2 w3) {
    float2 v;
    v = cmul(e[1], w1); float2 a0 = cadd(e[0], v), a1 = csub(e[0], v);
    v = cmul(e[3], w1); float2 a2 = cadd(e[2], v), a3 = csub(e[2], v);
    v = cmul(e[5], w1); float2 a4 = cadd(e[4], v), a5 = csub(e[4], v);
    v = cmul(e[7], w1); float2 a6 = cadd(e[6], v), a7 = csub(e[6], v);
    float2 iw2 = rot90(w2);
    v = cmul(a2, w2);  float2 b0 = cadd(a0, v), b2 = csub(a0, v);
    v = cmul(a3, iw2); float2 b1 = cadd(a1, v), b3 = csub(a1, v);
    v = cmul(a6, w2);  float2 b4 = cadd(a4, v), b6 = csub(a4, v);
    v = cmul(a7, iw2); float2 b5 = cadd(a5, v), b7 = csub(a5, v);
    const float C = 0.70710678118654752f;
    float2 uw3  = cmul(w3, make_float2(C, C));
    float2 iw3  = rot90(w3);
    float2 iuw3 = rot90(uw3);
    v = cmul(b4, w3);   e[0] = cadd(b0, v); e[4] = csub(b0, v);
    v = cmul(b5, uw3);  e[1] = cadd(b1, v); e[5] = csub(b1, v);
    v = cmul(b6, iw3);  e[2] = cadd(b2, v); e[6] = csub(b2, v);
    v = cmul(b7, iuw3); e[3] = cadd(b3, v); e[7] = csub(b3, v);
}

// fused radix-4 smem pass: stages S, S+1 (h = 2^(S-1)), twiddles from global
template <int S>
__device__ __forceinline__ void fpass(float2* xs, const float2* __restrict__ tws,
                                      int tid, int nbf) {
    const int h = 1 << (S - 1);
    for (int u = tid; u < nbf; u += 512) {
        int k    = u & (h - 1);
        int base = ((u >> (S - 1)) << (S + 1)) + k;
        int ia = XPAD(base), ib = XPAD(base + h);
        int ic = XPAD(base + 2 * h), id = XPAD(base + 3 * h);
        float2 a = xs[ia], b = xs[ib], c = xs[ic], d = xs[id];
        float2 w1 = ldtw(tws + h + k);
        float2 w2 = ldtw(tws + 2 * h + k);
        b = cmul(b, w1);
        d = cmul(d, w1);
        float2 t0 = cadd(a, b), t1 = csub(a, b);
        float2 t2 = cadd(c, d), t3 = csub(c, d);
        t2 = cmul(t2, w2);
        t3 = rot90(cmul(t3, w2));
        xs[ia] = cadd(t0, t2);
        xs[ic] = csub(t0, t2);
        xs[ib] = cadd(t1, t3);
        xs[id] = csub(t1, t3);
    }
}

// ---------------------------------------------------------------------------
// K1: masked transpose  T[k][p] = mask*(wr[p][k] + i*wi[p][k]),  k<=2048
// ---------------------------------------------------------------------------
__global__ void kern_mtrans(const float* __restrict__ wr, const float* __restrict__ wi,
                            const int* __restrict__ zmat) {
    __shared__ float2 tile[32][33];
    const int k0 = blockIdx.y * 32, p0 = blockIdx.x * 32;
    const int tx = threadIdx.x, ty = threadIdx.y;
#pragma unroll
    for (int j = 0; j < 32; j += 8) {
        int p = p0 + ty + j, k = k0 + tx;
        float2 v = make_float2(0.f, 0.f);
        if (k <= M_HALF) {
            size_t idx = (size_t)p * I_SZ + k;
            if (zmat[idx] <= 8388608)
                v = make_float2(wr[idx], wi[idx]);
        }
        tile[ty + j][tx] = v;
    }
    __syncthreads();
#pragma unroll
    for (int j = 0; j < 32; j += 8) {
        int k = k0 + ty + j;
        if (k <= M_HALF)
            g_T[(size_t)k * 4096 + p0 + tx] = tile[tx][ty + j];
    }
}

// ---------------------------------------------------------------------------
// K2: axis-0 IFFT (4096-pt) per column. Register radix-8 ends, 3 fused smem
// passes, twiddles direct from g_TW. Dynamic smem: [xs: 4368 f2]
// ---------------------------------------------------------------------------
#define FFT0_SMEM (4368 * 8)
__global__ __launch_bounds__(512) void kern_fft0() {
    extern __shared__ float2 dyn0[];
    float2* xs = dyn0;
    const int t = threadIdx.x;
    const int col = blockIdx.x;
    const float2 ONE = make_float2(1.f, 0.f);

    const float2* row = g_T + (size_t)col * 4096;
    const int g = __brev((unsigned)t) >> 23;   // brev9(t)
    float2 e[8];
    e[0] = row[t];          e[1] = row[t + 2048];
    e[2] = row[t + 1024];   e[3] = row[t + 3072];
    e[4] = row[t + 512];    e[5] = row[t + 2560];
    e[6] = row[t + 1536];   e[7] = row[t + 3584];
    radix8(e, ONE, ONE, ONE);
#pragma unroll
    for (int j = 0; j < 8; j++) xs[XPAD(8 * g + j)] = e[j];
    __syncthreads();

    fpass<4>(xs, g_TW, t, 1024);   // stages 4,5
    __syncthreads();
    fpass<6>(xs, g_TW, t, 1024);   // stages 6,7
    __syncthreads();
    fpass<8>(xs, g_TW, t, 1024);   // stages 8,9
    __syncthreads();

    float2 f[8];
#pragma unroll
    for (int j = 0; j < 8; j++) f[j] = xs[XPAD(t + 512 * j)];
    radix8(f, ldtw(g_TW + 512 + t), ldtw(g_TW + 1024 + t), ldtw(g_TW + 2048 + t));
    float2* out = g_U + (size_t)col * 4096;
#pragma unroll
    for (int j = 0; j < 8; j++) out[t + 512 * j] = f[j];
}

// ---------------------------------------------------------------------------
// K3: transpose back  H[p][k] = U[k][p]
// ---------------------------------------------------------------------------
__global__ void kern_trback() {
    __shared__ float2 tile[32][33];
    const int p0 = blockIdx.x * 32, k0 = blockIdx.y * 32;
    const int tx = threadIdx.x, ty = threadIdx.y;
#pragma unroll
    for (int j = 0; j < 32; j += 8) {
        int k = k0 + ty + j;
        tile[ty + j][tx] = (k <= M_HALF) ? g_U[(size_t)k * 4096 + p0 + tx]
                                         : make_float2(0.f, 0.f);
    }
    __syncthreads();
#pragma unroll
    for (int j = 0; j < 32; j += 8) {
        int k = k0 + tx;
        if (k <= M_HALF)
            g_T[(size_t)(p0 + ty + j) * HSTR + k] = tile[tx][ty + j];
    }
}

// ---------------------------------------------------------------------------
// K4: per row o: half-spectrum irfft (2048-pt IFFT + pack), register radix-8
// ends (t<256), fp16 out. Dynamic smem: [hbuf: 2049][xs: 2184]
// ---------------------------------------------------------------------------
#define IRFFT_SMEM ((2049 + 2184) * 8)
__global__ __launch_bounds__(512) void kern_irfft() {
    extern __shared__ float2 dyn1[];
    float2* hbuf = dyn1;
    float2* xs   = dyn1 + 2049;
    const int t = threadIdx.x;
    const int o = blockIdx.x;
    const float2 ONE = make_float2(1.f, 0.f);

    const float2* hrow = g_T + (size_t)o * HSTR;
    for (int k = t; k < 2049; k += 512) hbuf[k] = hrow[k];
    __syncthreads();

    if (t < 256) {
        const int g = __brev((unsigned)t) >> 24;   // brev8(t)
        const int B3[8] = {0, 4, 2, 6, 1, 5, 3, 7};
        float2 e[8];
#pragma unroll
        for (int j = 0; j < 8; j++) {
            int kk = t + 256 * B3[j];
            float2 Hk, Ck;
            if (kk == 0) {
                Hk = make_float2(hbuf[0].x, 0.f);
                Ck = make_float2(hbuf[M_HALF].x, 0.f);
            } else {
                Hk = hbuf[kk];
                float2 c = hbuf[M_HALF - kk];
                Ck = make_float2(c.x, -c.y);
            }
            float2 S = cadd(Hk, Ck);
            float2 D = csub(Hk, Ck);
            e[j] = cadd(S, rot90(cmul(D, ldtw(g_TW + 2048 + kk))));
        }
        radix8(e, ONE, ONE, ONE);
#pragma unroll
        for (int j = 0; j < 8; j++) xs[XPAD(8 * g + j)] = e[j];
    }
    __syncthreads();

    fpass<4>(xs, g_TW, t, 512);    // stages 4,5
    __syncthreads();
    fpass<6>(xs, g_TW, t, 512);    // stages 6,7
    __syncthreads();
    for (int u = t; u < 1024; u += 512) {   // single radix-2 stage 8
        int kk = u & 127;
        int i0 = ((u >> 7) << 8) + kk;
        int ia = XPAD(i0), ib = XPAD(i0 + 128);
        float2 w = ldtw(g_TW + 128 + kk);
        float2 uu = xs[ia], v = cmul(xs[ib], w);
        xs[ia] = cadd(uu, v);
        xs[ib] = csub(uu, v);
    }
    __syncthreads();

    if (t < 256) {
        float2 f[8];
#pragma unroll
        for (int j = 0; j < 8; j++) f[j] = xs[XPAD(t + 256 * j)];
        radix8(f, ldtw(g_TW + 256 + t), ldtw(g_TW + 512 + t), ldtw(g_TW + 1024 + t));
        const float s = 1.0f / 16777216.0f;
        __half* rowB = g_Bp + (size_t)o * KEXP;
#pragma unroll
        for (int j = 0; j < 8; j++) {
            int m = t + 256 * j;
            __half2 hp;
            hp.x = __float2half(f[j].x * s);
            hp.y = __float2half(f[j].y * s);
            *(__half2*)(rowB + 2 * m) = hp;
        }
    }
}

// ---------------------------------------------------------------------------
// convA: data -> fp16
// ---------------------------------------------------------------------------
__global__ __launch_bounds__(256) void kern_convA(const float* __restrict__ data) {
    size_t idx = ((size_t)blockIdx.x * 256 + threadIdx.x) * 4;
    float4 x = *(const float4*)(data + idx);
    __half2 h0, h1;
    h0.x = __float2half(x.x); h0.y = __float2half(x.y);
    h1.x = __float2half(x.z); h1.y = __float2half(x.w);
    *(__half2*)(g_Ap + idx)     = h0;
    *(__half2*)(g_Ap + idx + 2) = h1;
}

// ---------------------------------------------------------------------------
// mma.sync GEMM: CTA 128x128, 4 warps (2x2), warp tile 64x64, BK=64,
// 3-stage cp.async (96KB -> 2 CTAs/SM), prefetch-first single barrier.
// ---------------------------------------------------------------------------
#define GM 128
#define GN 128
#define TILE_K 64
#define STAGES 3
#define A_ST (GM * 128)                   // 16KB
#define B_ST (GN * 128)                   // 16KB
#define STAGE_BYTES (A_ST + B_ST)         // 32KB
#define NT (KEXP / TILE_K)                // 64
#define GEMM_SMEM (STAGES * STAGE_BYTES)  // 96KB

__global__ __launch_bounds__(128, 2) void kern_gemm_mma(const float* __restrict__ bias,
                                                        float* __restrict__ C) {
    extern __shared__ char dsm[];
    const uint32_t smem = smem_u32(dsm);
    const int tid  = threadIdx.x;
    const int wid  = tid >> 5;
    const int lane = tid & 31;
    const int m0   = (wid & 1) * 64;
    const int n0   = (wid >> 1) * 64;

    const __half* gA = g_Ap + (size_t)(blockIdx.y * GM) * KEXP;
    const __half* gB = g_Bp + (size_t)(blockIdx.x * GN) * KEXP;

    const int crow = tid >> 3;
    const int ccol = tid & 7;

    auto load_tile = [&](int t, int s) {
        const uint32_t sA = smem + s * STAGE_BYTES;
        const uint32_t sB = sA + A_ST;
        const char* srcA = (const char*)(gA + (size_t)t * TILE_K);
        const char* srcB = (const char*)(gB + (size_t)t * TILE_K);
#pragma unroll
        for (int r = 0; r < 8; r++) {
            int row = crow + r * 16;
            CP16(sA + swz(row, ccol * 16), srcA + (size_t)row * (KEXP * 2) + ccol * 16);
        }
#pragma unroll
        for (int r = 0; r < 8; r++) {
            int row = crow + r * 16;
            CP16(sB + swz(row, ccol * 16), srcB + (size_t)row * (KEXP * 2) + ccol * 16);
        }
    };

    float acc[4][8][4];
#pragma unroll
    for (int mt = 0; mt < 4; mt++)
#pragma unroll
        for (int nt = 0; nt < 8; nt++)
#pragma unroll
            for (int j = 0; j < 4; j++) acc[mt][nt][j] = 0.f;

    const int l7 = lane & 7;
    const int a_row = m0 + ((lane >> 3) & 1) * 8 + l7;
    const int a_kb  = ((lane >> 4) & 1) * 16;
    const int b_row = n0 + ((lane >> 4) & 1) * 8 + l7;
    const int b_kb  = ((lane >> 3) & 1) * 16;

    load_tile(0, 0); CP_COMMIT();
    load_tile(1, 1); CP_COMMIT();

#pragma unroll 1
    for (int t = 0; t < NT; t++) {
        asm volatile("cp.async.wait_group 1;" ::: "memory");
        __syncthreads();

        const int tn = t + 2;
        if (tn < NT) load_tile(tn, tn % STAGES);
        CP_COMMIT();

        const int s = t % STAGES;
        const uint32_t sA = smem + s * STAGE_BYTES;
        const uint32_t sB = sA + A_ST;

#pragma unroll
        for (int ks = 0; ks < 4; ks++) {
            const int kb = ks * 32;
            uint32_t a[4][4], b[8][2];
#pragma unroll
            for (int mt = 0; mt < 4; mt++) {
                uint32_t addr = sA + swz(a_row + mt * 16, kb + a_kb);
                LDSM_X4(a[mt][0], a[mt][1], a[mt][2], a[mt][3], addr);
            }
#pragma unroll
            for (int bt = 0; bt < 4; bt++) {
                uint32_t addr = sB + swz(b_row + bt * 16, kb + b_kb);
                LDSM_X4(b[2 * bt][0], b[2 * bt][1], b[2 * bt + 1][0], b[2 * bt + 1][1], addr);
            }
#pragma unroll
            for (int mt = 0; mt < 4; mt++)
#pragma unroll
                for (int nt = 0; nt < 8; nt++)
                    MMA16816(acc[mt][nt], a[mt], b[nt]);
        }
    }

    const int gid = lane >> 2;
    const int tig = lane & 3;
    float bv[8][2];
#pragma unroll
    for (int nt = 0; nt < 8; nt++) {
        const int col = blockIdx.x * GN + n0 + nt * 8 + 2 * tig;
        bv[nt][0] = __ldg(bias + col);
        bv[nt][1] = __ldg(bias + col + 1);
    }
#pragma unroll
    for (int mt = 0; mt < 4; mt++) {
        const int row0 = blockIdx.y * GM + m0 + mt * 16 + gid;
#pragma unroll
        for (int nt = 0; nt < 8; nt++) {
            const int col = blockIdx.x * GN + n0 + nt * 8 + 2 * tig;
            *(float2*)(C + (size_t)row0 * O_SZ + col) =
                make_float2(acc[mt][nt][0] + bv[nt][0], acc[mt][nt][1] + bv[nt][1]);
            *(float2*)(C + (size_t)(row0 + 8) * O_SZ + col) =
                make_float2(acc[mt][nt][2] + bv[nt][0], acc[mt][nt][3] + bv[nt][1]);
        }
    }
}

// ---------------------------------------------------------------------------
// Launch
// ---------------------------------------------------------------------------
extern "C" void kernel_launch(void* const* d_in, const int* in_sizes, int n_in,
                              void* d_out, int out_size) {
    const float* data = (const float*)d_in[0];
    const float* wr   = (const float*)d_in[1];
    const float* wi   = (const float*)d_in[2];
    const float* bias = (const float*)d_in[3];
    const int*   zmat = (const int*)d_in[4];
    float*       out  = (float*)d_out;

    cudaFuncSetAttribute(kern_gemm_mma, cudaFuncAttributeMaxDynamicSharedMemorySize, GEMM_SMEM);
    cudaFuncSetAttribute(kern_fft0,     cudaFuncAttributeMaxDynamicSharedMemorySize, FFT0_SMEM);
    cudaFuncSetAttribute(kern_irfft,    cudaFuncAttributeMaxDynamicSharedMemorySize, IRFFT_SMEM);

    kern_twinit<<<16, 256>>>();
    kern_convA<<<(B_SZ * I_SZ) / 1024, 256>>>(data);
    kern_mtrans<<<dim3(4096 / 32, 65), dim3(32, 8)>>>(wr, wi, zmat);
    kern_fft0<<<2049, 512, FFT0_SMEM>>>();
    kern_trback<<<dim3(4096 / 32, 65), dim3(32, 8)>>>();
    kern_irfft<<<O_SZ, 512, IRFFT_SMEM>>>();
    kern_gemm_mma<<<dim3(O_SZ / GN, B_SZ / GM), 128, GEMM_SMEM>>>(bias, out);
}

// round 14
// speedup vs baseline: 2.7659x; 1.0589x over previous
#include <cuda_runtime.h>
#include <cuda_fp16.h>
#include <cstdint>

#define B_SZ 2048
#define O_SZ 4096
#define I_SZ 4096
#define KEXP I_SZ                // 4096: plain fp16 A and B
#define M_HALF 2048              // I/2
#define HSTR 2056                // padded row stride for H (half2 units)

// padded smem index: breaks power-of-two stride bank conflicts
#define XPAD(i) ((i) + ((i) >> 4) + ((i) >> 8))

// ---------------------------------------------------------------------------
// Scratch (device globals: no allocation allowed). Spectral intermediates in
// half2 (re, im): T (masked spectrum), U (post axis-0 ifft, scaled 2^-6),
// H (U transposed).
// ---------------------------------------------------------------------------
__device__ __half2 g_T [(size_t)2049 * 4096];         // T[k][p]
__device__ __half2 g_U [(size_t)2049 * 4096];         // U[k][p] * 2^-6
__device__ __half2 g_H [(size_t)4096 * HSTR];         // H[p][k]
__device__ float2  g_TW[4096];                        // stage twiddles
__device__ __half  g_Ap[(size_t)B_SZ * KEXP];
__device__ __half  g_Bp[(size_t)O_SZ * KEXP];

// ---------------------------------------------------------------------------
// Helpers
// ---------------------------------------------------------------------------
__device__ __forceinline__ uint32_t smem_u32(const void* p) {
    uint32_t a;
    asm("{ .reg .u64 t; cvta.to.shared.u64 t, %1; cvt.u32.u64 %0, t; }" : "=r"(a) : "l"(p));
    return a;
}
__device__ __forceinline__ uint32_t swz(int row, int kb) {
    return (uint32_t)(row * 128 + (kb ^ ((row & 7) << 4)));
}
#define CP16(dst, src) asm volatile("cp.async.cg.shared.global [%0], [%1], 16;" :: "r"(dst), "l"(src) : "memory")
#define CP_COMMIT()    asm volatile("cp.async.commit_group;" ::: "memory")
#define LDSM_X4(r0, r1, r2, r3, addr) \
    asm volatile("ldmatrix.sync.aligned.m8n8.x4.shared.b16 {%0,%1,%2,%3}, [%4];" \
        : "=r"(r0), "=r"(r1), "=r"(r2), "=r"(r3) : "r"(addr))
#define MMA16816(d, a, b) \
    asm volatile("mma.sync.aligned.m16n8k16.row.col.f32.f16.f16.f32 " \
        "{%0,%1,%2,%3}, {%4,%5,%6,%7}, {%8,%9}, {%0,%1,%2,%3};" \
        : "+f"((d)[0]), "+f"((d)[1]), "+f"((d)[2]), "+f"((d)[3]) \
        : "r"((a)[0]), "r"((a)[1]), "r"((a)[2]), "r"((a)[3]), "r"((b)[0]), "r"((b)[1]))

__device__ __forceinline__ float2 cmul(float2 a, float2 b) {
    return make_float2(a.x * b.x - a.y * b.y, a.x * b.y + a.y * b.x);
}
__device__ __forceinline__ float2 cadd(float2 a, float2 b) { return make_float2(a.x + b.x, a.y + b.y); }
__device__ __forceinline__ float2 csub(float2 a, float2 b) { return make_float2(a.x - b.x, a.y - b.y); }
__device__ __forceinline__ float2 rot90(float2 a) { return make_float2(-a.y, a.x); }  // * i

__device__ __forceinline__ float2 h2f(__half2 h) {
    float2 v = __half22float2(h);
    return v;
}
__device__ __forceinline__ __half2 f2h(float2 v) {
    return __floats2half2_rn(v.x, v.y);
}
__device__ __forceinline__ float2 ldtw(const float2* __restrict__ p) {
    float2 v;
    v.x = __ldg(&p->x);
    v.y = __ldg(&p->y);
    return v;
}

// ---------------------------------------------------------------------------
// Twiddle table init (one-time): g_TW[2^(s-1)+k] = e^{+2*pi*i*k/2^s}
// ---------------------------------------------------------------------------
__global__ void kern_twinit() {
    int idx = blockIdx.x * 256 + threadIdx.x;
    if (idx == 0) { g_TW[0] = make_float2(1.f, 0.f); return; }
    int sm1 = 31 - __clz(idx);
    int k = idx - (1 << sm1);
    float ang = 6.283185307179586f * (float)k / (float)(1 << (sm1 + 1));
    float sn, cs;
    sincosf(ang, &sn, &cs);
    g_TW[idx] = make_float2(cs, sn);
}

// ---------------------------------------------------------------------------
// Register radix-8: three DIT stages (sign +).
// ---------------------------------------------------------------------------
__device__ __forceinline__ void radix8(float2 e[8], float2 w1, float2 w2, float2 w3) {
    float2 v;
    v = cmul(e[1], w1); float2 a0 = cadd(e[0], v), a1 = csub(e[0], v);
    v = cmul(e[3], w1); float2 a2 = cadd(e[2], v), a3 = csub(e[2], v);
    v = cmul(e[5], w1); float2 a4 = cadd(e[4], v), a5 = csub(e[4], v);
    v = cmul(e[7], w1); float2 a6 = cadd(e[6], v), a7 = csub(e[6], v);
    float2 iw2 = rot90(w2);
    v = cmul(a2, w2);  float2 b0 = cadd(a0, v), b2 = csub(a0, v);
    v = cmul(a3, iw2); float2 b1 = cadd(a1, v), b3 = csub(a1, v);
    v = cmul(a6, w2);  float2 b4 = cadd(a4, v), b6 = csub(a4, v);
    v = cmul(a7, iw2); float2 b5 = cadd(a5, v), b7 = csub(a5, v);
    const float C = 0.70710678118654752f;
    float2 uw3  = cmul(w3, make_float2(C, C));
    float2 iw3  = rot90(w3);
    float2 iuw3 = rot90(uw3);
    v = cmul(b4, w3);   e[0] = cadd(b0, v); e[4] = csub(b0, v);
    v = cmul(b5, uw3);  e[1] = cadd(b1, v); e[5] = csub(b1, v);
    v = cmul(b6, iw3);  e[2] = cadd(b2, v); e[6] = csub(b2, v);
    v = cmul(b7, iuw3); e[3] = cadd(b3, v); e[7] = csub(b3, v);
}

// fused radix-4 smem pass: stages S, S+1 (h = 2^(S-1)), twiddles from global
template <int S>
__device__ __forceinline__ void fpass(float2* xs, const float2* __restrict__ tws,
                                      int tid, int nbf) {
    const int h = 1 << (S - 1);
    for (int u = tid; u < nbf; u += 512) {
        int k    = u & (h - 1);
        int base = ((u >> (S - 1)) << (S + 1)) + k;
        int ia = XPAD(base), ib = XPAD(base + h);
        int ic = XPAD(base + 2 * h), id = XPAD(base + 3 * h);
        float2 a = xs[ia], b = xs[ib], c = xs[ic], d = xs[id];
        float2 w1 = ldtw(tws + h + k);
        float2 w2 = ldtw(tws + 2 * h + k);
        b = cmul(b, w1);
        d = cmul(d, w1);
        float2 t0 = cadd(a, b), t1 = csub(a, b);
        float2 t2 = cadd(c, d), t3 = csub(c, d);
        t2 = cmul(t2, w2);
        t3 = rot90(cmul(t3, w2));
        xs[ia] = cadd(t0, t2);
        xs[ic] = csub(t0, t2);
        xs[ib] = cadd(t1, t3);
        xs[id] = csub(t1, t3);
    }
}

// ---------------------------------------------------------------------------
// K1: masked transpose  T[k][p] = mask*(wr[p][k] + i*wi[p][k]),  k<=2048
// Output half2.
// ---------------------------------------------------------------------------
__global__ void kern_mtrans(const float* __restrict__ wr, const float* __restrict__ wi,
                            const int* __restrict__ zmat) {
    __shared__ __half2 tile[32][33];
    const int k0 = blockIdx.y * 32, p0 = blockIdx.x * 32;
    const int tx = threadIdx.x, ty = threadIdx.y;
#pragma unroll
    for (int j = 0; j < 32; j += 8) {
        int p = p0 + ty + j, k = k0 + tx;
        float2 v = make_float2(0.f, 0.f);
        if (k <= M_HALF) {
            size_t idx = (size_t)p * I_SZ + k;
            if (zmat[idx] <= 8388608)
                v = make_float2(wr[idx], wi[idx]);
        }
        tile[ty + j][tx] = f2h(v);
    }
    __syncthreads();
#pragma unroll
    for (int j = 0; j < 32; j += 8) {
        int k = k0 + ty + j;
        if (k <= M_HALF)
            g_T[(size_t)k * 4096 + p0 + tx] = tile[tx][ty + j];
    }
}

// ---------------------------------------------------------------------------
// K2: axis-0 IFFT (4096-pt) per column; half2 in, half2 out (scaled 2^-6).
// Dynamic smem: [xs: 4368 f2]
// ---------------------------------------------------------------------------
#define FFT0_SMEM (4368 * 8)
__global__ __launch_bounds__(512) void kern_fft0() {
    extern __shared__ float2 dyn0[];
    float2* xs = dyn0;
    const int t = threadIdx.x;
    const int col = blockIdx.x;
    const float2 ONE = make_float2(1.f, 0.f);

    const __half2* row = g_T + (size_t)col * 4096;
    const int g = __brev((unsigned)t) >> 23;   // brev9(t)
    float2 e[8];
    e[0] = h2f(row[t]);          e[1] = h2f(row[t + 2048]);
    e[2] = h2f(row[t + 1024]);   e[3] = h2f(row[t + 3072]);
    e[4] = h2f(row[t + 512]);    e[5] = h2f(row[t + 2560]);
    e[6] = h2f(row[t + 1536]);   e[7] = h2f(row[t + 3584]);
    radix8(e, ONE, ONE, ONE);
#pragma unroll
    for (int j = 0; j < 8; j++) xs[XPAD(8 * g + j)] = e[j];
    __syncthreads();

    fpass<4>(xs, g_TW, t, 1024);   // stages 4,5
    __syncthreads();
    fpass<6>(xs, g_TW, t, 1024);   // stages 6,7
    __syncthreads();
    fpass<8>(xs, g_TW, t, 1024);   // stages 8,9
    __syncthreads();

    float2 f[8];
#pragma unroll
    for (int j = 0; j < 8; j++) f[j] = xs[XPAD(t + 512 * j)];
    radix8(f, ldtw(g_TW + 512 + t), ldtw(g_TW + 1024 + t), ldtw(g_TW + 2048 + t));
    __half2* out = g_U + (size_t)col * 4096;
    const float sc = 0.015625f;    // 2^-6 range guard for fp16
#pragma unroll
    for (int j = 0; j < 8; j++)
        out[t + 512 * j] = f2h(make_float2(f[j].x * sc, f[j].y * sc));
}

// ---------------------------------------------------------------------------
// K3: transpose back  H[p][k] = U[k][p]  (half2)
// ---------------------------------------------------------------------------
__global__ void kern_trback() {
    __shared__ __half2 tile[32][33];
    const int p0 = blockIdx.x * 32, k0 = blockIdx.y * 32;
    const int tx = threadIdx.x, ty = threadIdx.y;
    const __half2 Z = __floats2half2_rn(0.f, 0.f);
#pragma unroll
    for (int j = 0; j < 32; j += 8) {
        int k = k0 + ty + j;
        tile[ty + j][tx] = (k <= M_HALF) ? g_U[(size_t)k * 4096 + p0 + tx] : Z;
    }
    __syncthreads();
#pragma unroll
    for (int j = 0; j < 32; j += 8) {
        int k = k0 + tx;
        if (k <= M_HALF)
            g_H[(size_t)(p0 + ty + j) * HSTR + k] = tile[tx][ty + j];
    }
}

// ---------------------------------------------------------------------------
// K4: per row o: half-spectrum irfft (2048-pt IFFT + pack), half2 in, fp16
// out. Final scale 2^-18 (2^-24 * 2^6 from fft0 pre-scale).
// Dynamic smem: [hbuf: 2049 half2][xs: 2184 f2]  (~26KB)
// ---------------------------------------------------------------------------
#define IRFFT_SMEM (2052 * 4 + 2184 * 8)
__global__ __launch_bounds__(512) void kern_irfft() {
    extern __shared__ char dyn1[];
    __half2* hbuf = (__half2*)dyn1;
    float2*  xs   = (float2*)(dyn1 + 2052 * 4);
    const int t = threadIdx.x;
    const int o = blockIdx.x;
    const float2 ONE = make_float2(1.f, 0.f);

    const __half2* hrow = g_H + (size_t)o * HSTR;
    for (int k = t; k < 2049; k += 512) hbuf[k] = hrow[k];
    __syncthreads();

    if (t < 256) {
        const int g = __brev((unsigned)t) >> 24;   // brev8(t)
        const int B3[8] = {0, 4, 2, 6, 1, 5, 3, 7};
        float2 e[8];
#pragma unroll
        for (int j = 0; j < 8; j++) {
            int kk = t + 256 * B3[j];
            float2 Hk, Ck;
            if (kk == 0) {
                Hk = make_float2(h2f(hbuf[0]).x, 0.f);
                Ck = make_float2(h2f(hbuf[M_HALF]).x, 0.f);
            } else {
                Hk = h2f(hbuf[kk]);
                float2 c = h2f(hbuf[M_HALF - kk]);
                Ck = make_float2(c.x, -c.y);
            }
            float2 S = cadd(Hk, Ck);
            float2 D = csub(Hk, Ck);
            e[j] = cadd(S, rot90(cmul(D, ldtw(g_TW + 2048 + kk))));
        }
        radix8(e, ONE, ONE, ONE);
#pragma unroll
        for (int j = 0; j < 8; j++) xs[XPAD(8 * g + j)] = e[j];
    }
    __syncthreads();

    fpass<4>(xs, g_TW, t, 512);    // stages 4,5
    __syncthreads();
    fpass<6>(xs, g_TW, t, 512);    // stages 6,7
    __syncthreads();
    for (int u = t; u < 1024; u += 512) {   // single radix-2 stage 8
        int kk = u & 127;
        int i0 = ((u >> 7) << 8) + kk;
        int ia = XPAD(i0), ib = XPAD(i0 + 128);
        float2 w = ldtw(g_TW + 128 + kk);
        float2 uu = xs[ia], v = cmul(xs[ib], w);
        xs[ia] = cadd(uu, v);
        xs[ib] = csub(uu, v);
    }
    __syncthreads();

    if (t < 256) {
        float2 f[8];
#pragma unroll
        for (int j = 0; j < 8; j++) f[j] = xs[XPAD(t + 256 * j)];
        radix8(f, ldtw(g_TW + 256 + t), ldtw(g_TW + 512 + t), ldtw(g_TW + 1024 + t));
        const float s = 1.0f / 262144.0f;   // 2^-18
        __half* rowB = g_Bp + (size_t)o * KEXP;
#pragma unroll
        for (int j = 0; j < 8; j++) {
            int m = t + 256 * j;
            __half2 hp;
            hp.x = __float2half(f[j].x * s);
            hp.y = __float2half(f[j].y * s);
            *(__half2*)(rowB + 2 * m) = hp;
        }
    }
}

// ---------------------------------------------------------------------------
// convA: data -> fp16
// ---------------------------------------------------------------------------
__global__ __launch_bounds__(256) void kern_convA(const float* __restrict__ data) {
    size_t idx = ((size_t)blockIdx.x * 256 + threadIdx.x) * 4;
    float4 x = *(const float4*)(data + idx);
    __half2 h0, h1;
    h0.x = __float2half(x.x); h0.y = __float2half(x.y);
    h1.x = __float2half(x.z); h1.y = __float2half(x.w);
    *(__half2*)(g_Ap + idx)     = h0;
    *(__half2*)(g_Ap + idx + 2) = h1;
}

// ---------------------------------------------------------------------------
// mma.sync GEMM: CTA 128x128, 4 warps (2x2), warp tile 64x64, BK=64,
// 3-stage cp.async (96KB -> 2 CTAs/SM), prefetch-first single barrier.
// ---------------------------------------------------------------------------
#define GM 128
#define GN 128
#define TILE_K 64
#define STAGES 3
#define A_ST (GM * 128)                   // 16KB
#define B_ST (GN * 128)                   // 16KB
#define STAGE_BYTES (A_ST + B_ST)         // 32KB
#define NT (KEXP / TILE_K)                // 64
#define GEMM_SMEM (STAGES * STAGE_BYTES)  // 96KB

__global__ __launch_bounds__(128, 2) void kern_gemm_mma(const float* __restrict__ bias,
                                                        float* __restrict__ C) {
    extern __shared__ char dsm[];
    const uint32_t smem = smem_u32(dsm);
    const int tid  = threadIdx.x;
    const int wid  = tid >> 5;
    const int lane = tid & 31;
    const int m0   = (wid & 1) * 64;
    const int n0   = (wid >> 1) * 64;

    const __half* gA = g_Ap + (size_t)(blockIdx.y * GM) * KEXP;
    const __half* gB = g_Bp + (size_t)(blockIdx.x * GN) * KEXP;

    const int crow = tid >> 3;
    const int ccol = tid & 7;

    auto load_tile = [&](int t, int s) {
        const uint32_t sA = smem + s * STAGE_BYTES;
        const uint32_t sB = sA + A_ST;
        const char* srcA = (const char*)(gA + (size_t)t * TILE_K);
        const char* srcB = (const char*)(gB + (size_t)t * TILE_K);
#pragma unroll
        for (int r = 0; r < 8; r++) {
            int row = crow + r * 16;
            CP16(sA + swz(row, ccol * 16), srcA + (size_t)row * (KEXP * 2) + ccol * 16);
        }
#pragma unroll
        for (int r = 0; r < 8; r++) {
            int row = crow + r * 16;
            CP16(sB + swz(row, ccol * 16), srcB + (size_t)row * (KEXP * 2) + ccol * 16);
        }
    };

    float acc[4][8][4];
#pragma unroll
    for (int mt = 0; mt < 4; mt++)
#pragma unroll
        for (int nt = 0; nt < 8; nt++)
#pragma unroll
            for (int j = 0; j < 4; j++) acc[mt][nt][j] = 0.f;

    const int l7 = lane & 7;
    const int a_row = m0 + ((lane >> 3) & 1) * 8 + l7;
    const int a_kb  = ((lane >> 4) & 1) * 16;
    const int b_row = n0 + ((lane >> 4) & 1) * 8 + l7;
    const int b_kb  = ((lane >> 3) & 1) * 16;

    load_tile(0, 0); CP_COMMIT();
    load_tile(1, 1); CP_COMMIT();

#pragma unroll 1
    for (int t = 0; t < NT; t++) {
        asm volatile("cp.async.wait_group 1;" ::: "memory");
        __syncthreads();

        const int tn = t + 2;
        if (tn < NT) load_tile(tn, tn % STAGES);
        CP_COMMIT();

        const int s = t % STAGES;
        const uint32_t sA = smem + s * STAGE_BYTES;
        const uint32_t sB = sA + A_ST;

#pragma unroll
        for (int ks = 0; ks < 4; ks++) {
            const int kb = ks * 32;
            uint32_t a[4][4], b[8][2];
#pragma unroll
            for (int mt = 0; mt < 4; mt++) {
                uint32_t addr = sA + swz(a_row + mt * 16, kb + a_kb);
                LDSM_X4(a[mt][0], a[mt][1], a[mt][2], a[mt][3], addr);
            }
#pragma unroll
            for (int bt = 0; bt < 4; bt++) {
                uint32_t addr = sB + swz(b_row + bt * 16, kb + b_kb);
                LDSM_X4(b[2 * bt][0], b[2 * bt][1], b[2 * bt + 1][0], b[2 * bt + 1][1], addr);
            }
#pragma unroll
            for (int mt = 0; mt < 4; mt++)
#pragma unroll
                for (int nt = 0; nt < 8; nt++)
                    MMA16816(acc[mt][nt], a[mt], b[nt]);
        }
    }

    const int gid = lane >> 2;
    const int tig = lane & 3;
    float bv[8][2];
#pragma unroll
    for (int nt = 0; nt < 8; nt++) {
        const int col = blockIdx.x * GN + n0 + nt * 8 + 2 * tig;
        bv[nt][0] = __ldg(bias + col);
        bv[nt][1] = __ldg(bias + col + 1);
    }
#pragma unroll
    for (int mt = 0; mt < 4; mt++) {
        const int row0 = blockIdx.y * GM + m0 + mt * 16 + gid;
#pragma unroll
        for (int nt = 0; nt < 8; nt++) {
            const int col = blockIdx.x * GN + n0 + nt * 8 + 2 * tig;
            *(float2*)(C + (size_t)row0 * O_SZ + col) =
                make_float2(acc[mt][nt][0] + bv[nt][0], acc[mt][nt][1] + bv[nt][1]);
            *(float2*)(C + (size_t)(row0 + 8) * O_SZ + col) =
                make_float2(acc[mt][nt][2] + bv[nt][0], acc[mt][nt][3] + bv[nt][1]);
        }
    }
}

// ---------------------------------------------------------------------------
// Launch
// ---------------------------------------------------------------------------
extern "C" void kernel_launch(void* const* d_in, const int* in_sizes, int n_in,
                              void* d_out, int out_size) {
    const float* data = (const float*)d_in[0];
    const float* wr   = (const float*)d_in[1];
    const float* wi   = (const float*)d_in[2];
    const float* bias = (const float*)d_in[3];
    const int*   zmat = (const int*)d_in[4];
    float*       out  = (float*)d_out;

    cudaFuncSetAttribute(kern_gemm_mma, cudaFuncAttributeMaxDynamicSharedMemorySize, GEMM_SMEM);
    cudaFuncSetAttribute(kern_fft0,     cudaFuncAttributeMaxDynamicSharedMemorySize, FFT0_SMEM);
    cudaFuncSetAttribute(kern_irfft,    cudaFuncAttributeMaxDynamicSharedMemorySize, IRFFT_SMEM);

    kern_twinit<<<16, 256>>>();
    kern_convA<<<(B_SZ * I_SZ) / 1024, 256>>>(data);
    kern_mtrans<<<dim3(4096 / 32, 65), dim3(32, 8)>>>(wr, wi, zmat);
    kern_fft0<<<2049, 512, FFT0_SMEM>>>();
    kern_trback<<<dim3(4096 / 32, 65), dim3(32, 8)>>>();
    kern_irfft<<<O_SZ, 512, IRFFT_SMEM>>>();
    kern_gemm_mma<<<dim3(O_SZ / GN, B_SZ / GM), 128, GEMM_SMEM>>>(bias, out);
}

// round 15
// speedup vs baseline: 2.9996x; 1.0845x over previous
#include <cuda_runtime.h>
#include <cuda_fp16.h>
#include <cstdint>

#define B_SZ 2048
#define O_SZ 4096
#define I_SZ 4096
#define KEXP I_SZ                // 4096: plain fp16 A and B
#define M_HALF 2048              // I/2
#define HSTR 2056                // padded row stride for H (half2 units)

#define XPAD(i) ((i) + ((i) >> 4) + ((i) >> 8))

// ---------------------------------------------------------------------------
// Scratch (device globals)
// ---------------------------------------------------------------------------
__device__ __half2 g_T [(size_t)2049 * 4096];         // T[k][p]
__device__ __half2 g_U [(size_t)2049 * 4096];         // U[k][p] * 2^-6
__device__ __half2 g_H [(size_t)4096 * HSTR];         // H[p][k]
__device__ float2  g_TW[4096];                        // stage twiddles
__device__ __half  g_Ap[(size_t)B_SZ * KEXP];
__device__ __half  g_Bp[(size_t)O_SZ * KEXP];

// ---------------------------------------------------------------------------
// Helpers
// ---------------------------------------------------------------------------
__device__ __forceinline__ uint32_t smem_u32(const void* p) {
    uint32_t a;
    asm("{ .reg .u64 t; cvta.to.shared.u64 t, %1; cvt.u32.u64 %0, t; }" : "=r"(a) : "l"(p));
    return a;
}
__device__ __forceinline__ uint32_t swz(int row, int kb) {
    return (uint32_t)(row * 128 + (kb ^ ((row & 7) << 4)));
}
#define CP16(dst, src) asm volatile("cp.async.cg.shared.global [%0], [%1], 16;" :: "r"(dst), "l"(src) : "memory")
#define CP_COMMIT()    asm volatile("cp.async.commit_group;" ::: "memory")
#define LDSM_X4(r0, r1, r2, r3, addr) \
    asm volatile("ldmatrix.sync.aligned.m8n8.x4.shared.b16 {%0,%1,%2,%3}, [%4];" \
        : "=r"(r0), "=r"(r1), "=r"(r2), "=r"(r3) : "r"(addr))
#define MMA16816(d, a, b) \
    asm volatile("mma.sync.aligned.m16n8k16.row.col.f32.f16.f16.f32 " \
        "{%0,%1,%2,%3}, {%4,%5,%6,%7}, {%8,%9}, {%0,%1,%2,%3};" \
        : "+f"((d)[0]), "+f"((d)[1]), "+f"((d)[2]), "+f"((d)[3]) \
        : "r"((a)[0]), "r"((a)[1]), "r"((a)[2]), "r"((a)[3]), "r"((b)[0]), "r"((b)[1]))

__device__ __forceinline__ float2 cmul(float2 a, float2 b) {
    return make_float2(a.x * b.x - a.y * b.y, a.x * b.y + a.y * b.x);
}
__device__ __forceinline__ float2 cadd(float2 a, float2 b) { return make_float2(a.x + b.x, a.y + b.y); }
__device__ __forceinline__ float2 csub(float2 a, float2 b) { return make_float2(a.x - b.x, a.y - b.y); }
__device__ __forceinline__ float2 rot90(float2 a) { return make_float2(-a.y, a.x); }

__device__ __forceinline__ float2 h2f(__half2 h) { return __half22float2(h); }
__device__ __forceinline__ __half2 f2h(float2 v) { return __floats2half2_rn(v.x, v.y); }
__device__ __forceinline__ float2 ldtw(const float2* __restrict__ p) {
    float2 v;
    v.x = __ldg(&p->x);
    v.y = __ldg(&p->y);
    return v;
}

// ---------------------------------------------------------------------------
// Register radix-8: three DIT stages (sign +).
// ---------------------------------------------------------------------------
__device__ __forceinline__ void radix8(float2 e[8], float2 w1, float2 w2, float2 w3) {
    float2 v;
    v = cmul(e[1], w1); float2 a0 = cadd(e[0], v), a1 = csub(e[0], v);
    v = cmul(e[3], w1); float2 a2 = cadd(e[2], v), a3 = csub(e[2], v);
    v = cmul(e[5], w1); float2 a4 = cadd(e[4], v), a5 = csub(e[4], v);
    v = cmul(e[7], w1); float2 a6 = cadd(e[6], v), a7 = csub(e[6], v);
    float2 iw2 = rot90(w2);
    v = cmul(a2, w2);  float2 b0 = cadd(a0, v), b2 = csub(a0, v);
    v = cmul(a3, iw2); float2 b1 = cadd(a1, v), b3 = csub(a1, v);
    v = cmul(a6, w2);  float2 b4 = cadd(a4, v), b6 = csub(a4, v);
    v = cmul(a7, iw2); float2 b5 = cadd(a5, v), b7 = csub(a5, v);
    const float C = 0.70710678118654752f;
    float2 uw3  = cmul(w3, make_float2(C, C));
    float2 iw3  = rot90(w3);
    float2 iuw3 = rot90(uw3);
    v = cmul(b4, w3);   e[0] = cadd(b0, v); e[4] = csub(b0, v);
    v = cmul(b5, uw3);  e[1] = cadd(b1, v); e[5] = csub(b1, v);
    v = cmul(b6, iw3);  e[2] = cadd(b2, v); e[6] = csub(b2, v);
    v = cmul(b7, iuw3); e[3] = cadd(b3, v); e[7] = csub(b3, v);
}

template <int S>
__device__ __forceinline__ void fpass(float2* xs, const float2* __restrict__ tws,
                                      int tid, int nbf) {
    const int h = 1 << (S - 1);
    for (int u = tid; u < nbf; u += 512) {
        int k    = u & (h - 1);
        int base = ((u >> (S - 1)) << (S + 1)) + k;
        int ia = XPAD(base), ib = XPAD(base + h);
        int ic = XPAD(base + 2 * h), id = XPAD(base + 3 * h);
        float2 a = xs[ia], b = xs[ib], c = xs[ic], d = xs[id];
        float2 w1 = ldtw(tws + h + k);
        float2 w2 = ldtw(tws + 2 * h + k);
        b = cmul(b, w1);
        d = cmul(d, w1);
        float2 t0 = cadd(a, b), t1 = csub(a, b);
        float2 t2 = cadd(c, d), t3 = csub(c, d);
        t2 = cmul(t2, w2);
        t3 = rot90(cmul(t3, w2));
        xs[ia] = cadd(t0, t2);
        xs[ic] = csub(t0, t2);
        xs[ib] = cadd(t1, t3);
        xs[id] = csub(t1, t3);
    }
}

// ---------------------------------------------------------------------------
// convA: data -> fp16; first 16 blocks also build the twiddle table.
// ---------------------------------------------------------------------------
__global__ __launch_bounds__(256) void kern_convA(const float* __restrict__ data) {
    if (blockIdx.x < 16) {
        int idx = blockIdx.x * 256 + threadIdx.x;
        if (idx == 0) {
            g_TW[0] = make_float2(1.f, 0.f);
        } else {
            int sm1 = 31 - __clz(idx);
            int k = idx - (1 << sm1);
            float ang = 6.283185307179586f * (float)k / (float)(1 << (sm1 + 1));
            float sn, cs;
            sincosf(ang, &sn, &cs);
            g_TW[idx] = make_float2(cs, sn);
        }
    }
    size_t idx = ((size_t)blockIdx.x * 256 + threadIdx.x) * 4;
    float4 x = *(const float4*)(data + idx);
    __half2 h0, h1;
    h0.x = __float2half(x.x); h0.y = __float2half(x.y);
    h1.x = __float2half(x.z); h1.y = __float2half(x.w);
    *(__half2*)(g_Ap + idx)     = h0;
    *(__half2*)(g_Ap + idx + 2) = h1;
}

// ---------------------------------------------------------------------------
// K1: masked transpose  T[k][p] = mask*(wr[p][k] + i*wi[p][k]),  k<=2048
// ---------------------------------------------------------------------------
__global__ void kern_mtrans(const float* __restrict__ wr, const float* __restrict__ wi,
                            const int* __restrict__ zmat) {
    __shared__ __half2 tile[32][33];
    const int k0 = blockIdx.y * 32, p0 = blockIdx.x * 32;
    const int tx = threadIdx.x, ty = threadIdx.y;
#pragma unroll
    for (int j = 0; j < 32; j += 8) {
        int p = p0 + ty + j, k = k0 + tx;
        float2 v = make_float2(0.f, 0.f);
        if (k <= M_HALF) {
            size_t idx = (size_t)p * I_SZ + k;
            if (zmat[idx] <= 8388608)
                v = make_float2(wr[idx], wi[idx]);
        }
        tile[ty + j][tx] = f2h(v);
    }
    __syncthreads();
#pragma unroll
    for (int j = 0; j < 32; j += 8) {
        int k = k0 + ty + j;
        if (k <= M_HALF)
            g_T[(size_t)k * 4096 + p0 + tx] = tile[tx][ty + j];
    }
}

// ---------------------------------------------------------------------------
// K2: axis-0 IFFT (4096-pt) per column; half2 in, half2 out (scaled 2^-6).
// ---------------------------------------------------------------------------
#define FFT0_SMEM (4368 * 8)
__global__ __launch_bounds__(512) void kern_fft0() {
    extern __shared__ float2 dyn0[];
    float2* xs = dyn0;
    const int t = threadIdx.x;
    const int col = blockIdx.x;
    const float2 ONE = make_float2(1.f, 0.f);

    const __half2* row = g_T + (size_t)col * 4096;
    const int g = __brev((unsigned)t) >> 23;
    float2 e[8];
    e[0] = h2f(row[t]);          e[1] = h2f(row[t + 2048]);
    e[2] = h2f(row[t + 1024]);   e[3] = h2f(row[t + 3072]);
    e[4] = h2f(row[t + 512]);    e[5] = h2f(row[t + 2560]);
    e[6] = h2f(row[t + 1536]);   e[7] = h2f(row[t + 3584]);
    radix8(e, ONE, ONE, ONE);
#pragma unroll
    for (int j = 0; j < 8; j++) xs[XPAD(8 * g + j)] = e[j];
    __syncthreads();

    fpass<4>(xs, g_TW, t, 1024);
    __syncthreads();
    fpass<6>(xs, g_TW, t, 1024);
    __syncthreads();
    fpass<8>(xs, g_TW, t, 1024);
    __syncthreads();

    float2 f[8];
#pragma unroll
    for (int j = 0; j < 8; j++) f[j] = xs[XPAD(t + 512 * j)];
    radix8(f, ldtw(g_TW + 512 + t), ldtw(g_TW + 1024 + t), ldtw(g_TW + 2048 + t));
    __half2* out = g_U + (size_t)col * 4096;
    const float sc = 0.015625f;
#pragma unroll
    for (int j = 0; j < 8; j++)
        out[t + 512 * j] = f2h(make_float2(f[j].x * sc, f[j].y * sc));
}

// ---------------------------------------------------------------------------
// K3: transpose back  H[p][k] = U[k][p]
// ---------------------------------------------------------------------------
__global__ void kern_trback() {
    __shared__ __half2 tile[32][33];
    const int p0 = blockIdx.x * 32, k0 = blockIdx.y * 32;
    const int tx = threadIdx.x, ty = threadIdx.y;
    const __half2 Z = __floats2half2_rn(0.f, 0.f);
#pragma unroll
    for (int j = 0; j < 32; j += 8) {
        int k = k0 + ty + j;
        tile[ty + j][tx] = (k <= M_HALF) ? g_U[(size_t)k * 4096 + p0 + tx] : Z;
    }
    __syncthreads();
#pragma unroll
    for (int j = 0; j < 32; j += 8) {
        int k = k0 + tx;
        if (k <= M_HALF)
            g_H[(size_t)(p0 + ty + j) * HSTR + k] = tile[tx][ty + j];
    }
}

// ---------------------------------------------------------------------------
// K4: per row o: half-spectrum irfft, fp16 out. Final scale 2^-18.
// ---------------------------------------------------------------------------
#define IRFFT_SMEM (2052 * 4 + 2184 * 8)
__global__ __launch_bounds__(512) void kern_irfft() {
    extern __shared__ char dyn1[];
    __half2* hbuf = (__half2*)dyn1;
    float2*  xs   = (float2*)(dyn1 + 2052 * 4);
    const int t = threadIdx.x;
    const int o = blockIdx.x;
    const float2 ONE = make_float2(1.f, 0.f);

    const __half2* hrow = g_H + (size_t)o * HSTR;
    for (int k = t; k < 2049; k += 512) hbuf[k] = hrow[k];
    __syncthreads();

    if (t < 256) {
        const int g = __brev((unsigned)t) >> 24;
        const int B3[8] = {0, 4, 2, 6, 1, 5, 3, 7};
        float2 e[8];
#pragma unroll
        for (int j = 0; j < 8; j++) {
            int kk = t + 256 * B3[j];
            float2 Hk, Ck;
            if (kk == 0) {
                Hk = make_float2(h2f(hbuf[0]).x, 0.f);
                Ck = make_float2(h2f(hbuf[M_HALF]).x, 0.f);
            } else {
                Hk = h2f(hbuf[kk]);
                float2 c = h2f(hbuf[M_HALF - kk]);
                Ck = make_float2(c.x, -c.y);
            }
            float2 S = cadd(Hk, Ck);
            float2 D = csub(Hk, Ck);
            e[j] = cadd(S, rot90(cmul(D, ldtw(g_TW + 2048 + kk))));
        }
        radix8(e, ONE, ONE, ONE);
#pragma unroll
        for (int j = 0; j < 8; j++) xs[XPAD(8 * g + j)] = e[j];
    }
    __syncthreads();

    fpass<4>(xs, g_TW, t, 512);
    __syncthreads();
    fpass<6>(xs, g_TW, t, 512);
    __syncthreads();
    for (int u = t; u < 1024; u += 512) {
        int kk = u & 127;
        int i0 = ((u >> 7) << 8) + kk;
        int ia = XPAD(i0), ib = XPAD(i0 + 128);
        float2 w = ldtw(g_TW + 128 + kk);
        float2 uu = xs[ia], v = cmul(xs[ib], w);
        xs[ia] = cadd(uu, v);
        xs[ib] = csub(uu, v);
    }
    __syncthreads();

    if (t < 256) {
        float2 f[8];
#pragma unroll
        for (int j = 0; j < 8; j++) f[j] = xs[XPAD(t + 256 * j)];
        radix8(f, ldtw(g_TW + 256 + t), ldtw(g_TW + 512 + t), ldtw(g_TW + 1024 + t));
        const float s = 1.0f / 262144.0f;   // 2^-18
        __half* rowB = g_Bp + (size_t)o * KEXP;
#pragma unroll
        for (int j = 0; j < 8; j++) {
            int m = t + 256 * j;
            __half2 hp;
            hp.x = __float2half(f[j].x * s);
            hp.y = __float2half(f[j].y * s);
            *(__half2*)(rowB + 2 * m) = hp;
        }
    }
}

// ---------------------------------------------------------------------------
// mma.sync GEMM: CTA 64x128 (fine tiles for ~1% wave quantization),
// 4 warps (2Mx2N), warp tile 32x64, BK=64, 3-stage cp.async
// (24KB/stage -> 72KB -> 3 CTAs/SM), prefetch-first single barrier.
// ---------------------------------------------------------------------------
#define GM 64
#define GN 128
#define TILE_K 64
#define STAGES 3
#define A_ST (GM * 128)                   // 8KB
#define B_ST (GN * 128)                   // 16KB
#define STAGE_BYTES (A_ST + B_ST)         // 24KB
#define NT (KEXP / TILE_K)                // 64
#define GEMM_SMEM (STAGES * STAGE_BYTES)  // 72KB

__global__ __launch_bounds__(128, 3) void kern_gemm_mma(const float* __restrict__ bias,
                                                        float* __restrict__ C) {
    extern __shared__ char dsm[];
    const uint32_t smem = smem_u32(dsm);
    const int tid  = threadIdx.x;
    const int wid  = tid >> 5;
    const int lane = tid & 31;
    const int m0   = (wid & 1) * 32;       // warp M origin (0, 32)
    const int n0   = (wid >> 1) * 64;      // warp N origin (0, 64)

    const __half* gA = g_Ap + (size_t)(blockIdx.y * GM) * KEXP;
    const __half* gB = g_Bp + (size_t)(blockIdx.x * GN) * KEXP;

    const int crow = tid >> 3;             // 0..15
    const int ccol = tid & 7;              // 0..7

    auto load_tile = [&](int t, int s) {
        const uint32_t sA = smem + s * STAGE_BYTES;
        const uint32_t sB = sA + A_ST;
        const char* srcA = (const char*)(gA + (size_t)t * TILE_K);
        const char* srcB = (const char*)(gB + (size_t)t * TILE_K);
#pragma unroll
        for (int r = 0; r < 4; r++) {      // A: 64 rows
            int row = crow + r * 16;
            CP16(sA + swz(row, ccol * 16), srcA + (size_t)row * (KEXP * 2) + ccol * 16);
        }
#pragma unroll
        for (int r = 0; r < 8; r++) {      // B: 128 rows
            int row = crow + r * 16;
            CP16(sB + swz(row, ccol * 16), srcB + (size_t)row * (KEXP * 2) + ccol * 16);
        }
    };

    float acc[2][8][4];
#pragma unroll
    for (int mt = 0; mt < 2; mt++)
#pragma unroll
        for (int nt = 0; nt < 8; nt++)
#pragma unroll
            for (int j = 0; j < 4; j++) acc[mt][nt][j] = 0.f;

    const int l7 = lane & 7;
    const int a_row = m0 + ((lane >> 3) & 1) * 8 + l7;
    const int a_kb  = ((lane >> 4) & 1) * 16;
    const int b_row = n0 + ((lane >> 4) & 1) * 8 + l7;
    const int b_kb  = ((lane >> 3) & 1) * 16;

    load_tile(0, 0); CP_COMMIT();
    load_tile(1, 1); CP_COMMIT();

#pragma unroll 1
    for (int t = 0; t < NT; t++) {
        asm volatile("cp.async.wait_group 1;" ::: "memory");
        __syncthreads();

        const int tn = t + 2;
        if (tn < NT) load_tile(tn, tn % STAGES);
        CP_COMMIT();

        const int s = t % STAGES;
        const uint32_t sA = smem + s * STAGE_BYTES;
        const uint32_t sB = sA + A_ST;

#pragma unroll
        for (int ks = 0; ks < 4; ks++) {
            const int kb = ks * 32;
            uint32_t a[2][4], b[8][2];
#pragma unroll
            for (int mt = 0; mt < 2; mt++) {
                uint32_t addr = sA + swz(a_row + mt * 16, kb + a_kb);
                LDSM_X4(a[mt][0], a[mt][1], a[mt][2], a[mt][3], addr);
            }
#pragma unroll
            for (int bt = 0; bt < 4; bt++) {
                uint32_t addr = sB + swz(b_row + bt * 16, kb + b_kb);
                LDSM_X4(b[2 * bt][0], b[2 * bt][1], b[2 * bt + 1][0], b[2 * bt + 1][1], addr);
            }
#pragma unroll
            for (int mt = 0; mt < 2; mt++)
#pragma unroll
                for (int nt = 0; nt < 8; nt++)
                    MMA16816(acc[mt][nt], a[mt], b[nt]);
        }
    }

    const int gid = lane >> 2;
    const int tig = lane & 3;
    float bv[8][2];
#pragma unroll
    for (int nt = 0; nt < 8; nt++) {
        const int col = blockIdx.x * GN + n0 + nt * 8 + 2 * tig;
        bv[nt][0] = __ldg(bias + col);
        bv[nt][1] = __ldg(bias + col + 1);
    }
#pragma unroll
    for (int mt = 0; mt < 2; mt++) {
        const int row0 = blockIdx.y * GM + m0 + mt * 16 + gid;
#pragma unroll
        for (int nt = 0; nt < 8; nt++) {
            const int col = blockIdx.x * GN + n0 + nt * 8 + 2 * tig;
            *(float2*)(C + (size_t)row0 * O_SZ + col) =
                make_float2(acc[mt][nt][0] + bv[nt][0], acc[mt][nt][1] + bv[nt][1]);
            *(float2*)(C + (size_t)(row0 + 8) * O_SZ + col) =
                make_float2(acc[mt][nt][2] + bv[nt][0], acc[mt][nt][3] + bv[nt][1]);
        }
    }
}

// ---------------------------------------------------------------------------
// Launch
// ---------------------------------------------------------------------------
extern "C" void kernel_launch(void* const* d_in, const int* in_sizes, int n_in,
                              void* d_out, int out_size) {
    const float* data = (const float*)d_in[0];
    const float* wr   = (const float*)d_in[1];
    const float* wi   = (const float*)d_in[2];
    const float* bias = (const float*)d_in[3];
    const int*   zmat = (const int*)d_in[4];
    float*       out  = (float*)d_out;

    cudaFuncSetAttribute(kern_gemm_mma, cudaFuncAttributeMaxDynamicSharedMemorySize, GEMM_SMEM);
    cudaFuncSetAttribute(kern_fft0,     cudaFuncAttributeMaxDynamicSharedMemorySize, FFT0_SMEM);
    cudaFuncSetAttribute(kern_irfft,    cudaFuncAttributeMaxDynamicSharedMemorySize, IRFFT_SMEM);

    kern_convA<<<(B_SZ * I_SZ) / 1024, 256>>>(data);
    kern_mtrans<<<dim3(4096 / 32, 65), dim3(32, 8)>>>(wr, wi, zmat);
    kern_fft0<<<2049, 512, FFT0_SMEM>>>();
    kern_trback<<<dim3(4096 / 32, 65), dim3(32, 8)>>>();
    kern_irfft<<<O_SZ, 512, IRFFT_SMEM>>>();
    kern_gemm_mma<<<dim3(O_SZ / GN, B_SZ / GM), 128, GEMM_SMEM>>>(bias, out);
}

// round 17
// speedup vs baseline: 3.0218x; 1.0074x over previous
#include <cuda_runtime.h>
#include <cuda_fp16.h>
#include <cstdint>

#define B_SZ 2048
#define O_SZ 4096
#define I_SZ 4096
#define KEXP I_SZ                // 4096: plain fp16 A and B
#define M_HALF 2048              // I/2
#define HSTR 2056                // padded row stride for H (half2 units)

#define XPAD(i) ((i) + ((i) >> 4) + ((i) >> 8))

// ---------------------------------------------------------------------------
// Scratch (device globals)
// ---------------------------------------------------------------------------
__device__ __half2 g_T [(size_t)2049 * 4096];         // T[k][p]
__device__ __half2 g_U [(size_t)2049 * 4096];         // U[k][p] * 2^-6
__device__ __half2 g_H [(size_t)4096 * HSTR];         // H[p][k]
__device__ float2  g_TW[4096];                        // stage twiddles
__device__ __half  g_Ap[(size_t)B_SZ * KEXP];
__device__ __half  g_Bp[(size_t)O_SZ * KEXP];

// ---------------------------------------------------------------------------
// Helpers
// ---------------------------------------------------------------------------
__device__ __forceinline__ uint32_t smem_u32(const void* p) {
    uint32_t a;
    asm("{ .reg .u64 t; cvta.to.shared.u64 t, %1; cvt.u32.u64 %0, t; }" : "=r"(a) : "l"(p));
    return a;
}
__device__ __forceinline__ uint32_t swz(int row, int kb) {
    return (uint32_t)(row * 128 + (kb ^ ((row & 7) << 4)));
}
#define CP16(dst, src) asm volatile("cp.async.cg.shared.global [%0], [%1], 16;" :: "r"(dst), "l"(src) : "memory")
#define CP_COMMIT()    asm volatile("cp.async.commit_group;" ::: "memory")
#define LDSM_X4(r0, r1, r2, r3, addr) \
    asm volatile("ldmatrix.sync.aligned.m8n8.x4.shared.b16 {%0,%1,%2,%3}, [%4];" \
        : "=r"(r0), "=r"(r1), "=r"(r2), "=r"(r3) : "r"(addr))
#define MMA16816(d, a, b) \
    asm volatile("mma.sync.aligned.m16n8k16.row.col.f32.f16.f16.f32 " \
        "{%0,%1,%2,%3}, {%4,%5,%6,%7}, {%8,%9}, {%0,%1,%2,%3};" \
        : "+f"((d)[0]), "+f"((d)[1]), "+f"((d)[2]), "+f"((d)[3]) \
        : "r"((a)[0]), "r"((a)[1]), "r"((a)[2]), "r"((a)[3]), "r"((b)[0]), "r"((b)[1]))

__device__ __forceinline__ float2 cmul(float2 a, float2 b) {
    return make_float2(a.x * b.x - a.y * b.y, a.x * b.y + a.y * b.x);
}
__device__ __forceinline__ float2 cadd(float2 a, float2 b) { return make_float2(a.x + b.x, a.y + b.y); }
__device__ __forceinline__ float2 csub(float2 a, float2 b) { return make_float2(a.x - b.x, a.y - b.y); }
__device__ __forceinline__ float2 rot90(float2 a) { return make_float2(-a.y, a.x); }

__device__ __forceinline__ float2 h2f(__half2 h) { return __half22float2(h); }
__device__ __forceinline__ __half2 f2h(float2 v) { return __floats2half2_rn(v.x, v.y); }
__device__ __forceinline__ float2 ldtw(const float2* __restrict__ p) {
    float2 v;
    v.x = __ldg(&p->x);
    v.y = __ldg(&p->y);
    return v;
}

// ---------------------------------------------------------------------------
// Register radix-8: three DIT stages (sign +).
// ---------------------------------------------------------------------------
__device__ __forceinline__ void radix8(float2 e[8], float2 w1, float2 w2, float2 w3) {
    float2 v;
    v = cmul(e[1], w1); float2 a0 = cadd(e[0], v), a1 = csub(e[0], v);
    v = cmul(e[3], w1); float2 a2 = cadd(e[2], v), a3 = csub(e[2], v);
    v = cmul(e[5], w1); float2 a4 = cadd(e[4], v), a5 = csub(e[4], v);
    v = cmul(e[7], w1); float2 a6 = cadd(e[6], v), a7 = csub(e[6], v);
    float2 iw2 = rot90(w2);
    v = cmul(a2, w2);  float2 b0 = cadd(a0, v), b2 = csub(a0, v);
    v = cmul(a3, iw2); float2 b1 = cadd(a1, v), b3 = csub(a1, v);
    v = cmul(a6, w2);  float2 b4 = cadd(a4, v), b6 = csub(a4, v);
    v = cmul(a7, iw2); float2 b5 = cadd(a5, v), b7 = csub(a5, v);
    const float C = 0.70710678118654752f;
    float2 uw3  = cmul(w3, make_float2(C, C));
    float2 iw3  = rot90(w3);
    float2 iuw3 = rot90(uw3);
    v = cmul(b4, w3);   e[0] = cadd(b0, v); e[4] = csub(b0, v);
    v = cmul(b5, uw3);  e[1] = cadd(b1, v); e[5] = csub(b1, v);
    v = cmul(b6, iw3);  e[2] = cadd(b2, v); e[6] = csub(b2, v);
    v = cmul(b7, iuw3); e[3] = cadd(b3, v); e[7] = csub(b3, v);
}

template <int S>
__device__ __forceinline__ void fpass(float2* xs, const float2* __restrict__ tws,
                                      int tid, int nbf) {
    const int h = 1 << (S - 1);
    for (int u = tid; u < nbf; u += 512) {
        int k    = u & (h - 1);
        int base = ((u >> (S - 1)) << (S + 1)) + k;
        int ia = XPAD(base), ib = XPAD(base + h);
        int ic = XPAD(base + 2 * h), id = XPAD(base + 3 * h);
        float2 a = xs[ia], b = xs[ib], c = xs[ic], d = xs[id];
        float2 w1 = ldtw(tws + h + k);
        float2 w2 = ldtw(tws + 2 * h + k);
        b = cmul(b, w1);
        d = cmul(d, w1);
        float2 t0 = cadd(a, b), t1 = csub(a, b);
        float2 t2 = cadd(c, d), t3 = csub(c, d);
        t2 = cmul(t2, w2);
        t3 = rot90(cmul(t3, w2));
        xs[ia] = cadd(t0, t2);
        xs[ic] = csub(t0, t2);
        xs[ib] = cadd(t1, t3);
        xs[id] = csub(t1, t3);
    }
}

// ---------------------------------------------------------------------------
// K1: fused kernel.
//   y < 65 : masked transpose  T[k][p] = mask*(wr[p][k] + i*wi[p][k])
//   y >= 65: aux slices, bid = (y-65)*128 + x in [0, 8320):
//              bid < 8192  -> convA (data -> fp16), 8192*256*4 = 8.4M elems
//              bid < 8208  -> twiddle table build (16*256 = 4096 entries)
// ---------------------------------------------------------------------------
__global__ void kern_mtrans(const float* __restrict__ wr, const float* __restrict__ wi,
                            const int* __restrict__ zmat,
                            const float* __restrict__ data) {
    const int tx = threadIdx.x, ty = threadIdx.y;
    if (blockIdx.y >= 65) {
        const int bid = (blockIdx.y - 65) * 128 + blockIdx.x;   // 0..8319
        const int tid = ty * 32 + tx;                           // 0..255
        if (bid < 8192) {
            size_t idx = ((size_t)bid * 256 + tid) * 4;
            float4 x = *(const float4*)(data + idx);
            __half2 h0, h1;
            h0.x = __float2half(x.x); h0.y = __float2half(x.y);
            h1.x = __float2half(x.z); h1.y = __float2half(x.w);
            *(__half2*)(g_Ap + idx)     = h0;
            *(__half2*)(g_Ap + idx + 2) = h1;
        } else if (bid < 8208) {
            int idx = (bid - 8192) * 256 + tid;                 // 0..4095
            if (idx == 0) {
                g_TW[0] = make_float2(1.f, 0.f);
            } else {
                int sm1 = 31 - __clz(idx);
                int k = idx - (1 << sm1);
                float ang = 6.283185307179586f * (float)k / (float)(1 << (sm1 + 1));
                float sn, cs;
                sincosf(ang, &sn, &cs);
                g_TW[idx] = make_float2(cs, sn);
            }
        }
        return;
    }

    __shared__ __half2 tile[32][33];
    const int k0 = blockIdx.y * 32, p0 = blockIdx.x * 32;
#pragma unroll
    for (int j = 0; j < 32; j += 8) {
        int p = p0 + ty + j, k = k0 + tx;
        float2 v = make_float2(0.f, 0.f);
        if (k <= M_HALF) {
            size_t idx = (size_t)p * I_SZ + k;
            if (zmat[idx] <= 8388608)
                v = make_float2(wr[idx], wi[idx]);
        }
        tile[ty + j][tx] = f2h(v);
    }
    __syncthreads();
#pragma unroll
    for (int j = 0; j < 32; j += 8) {
        int k = k0 + ty + j;
        if (k <= M_HALF)
            g_T[(size_t)k * 4096 + p0 + tx] = tile[tx][ty + j];
    }
}

// ---------------------------------------------------------------------------
// K2: axis-0 IFFT (4096-pt) per column; half2 in, half2 out (scaled 2^-6).
// ---------------------------------------------------------------------------
#define FFT0_SMEM (4368 * 8)
__global__ __launch_bounds__(512) void kern_fft0() {
    extern __shared__ float2 dyn0[];
    float2* xs = dyn0;
    const int t = threadIdx.x;
    const int col = blockIdx.x;
    const float2 ONE = make_float2(1.f, 0.f);

    const __half2* row = g_T + (size_t)col * 4096;
    const int g = __brev((unsigned)t) >> 23;
    float2 e[8];
    e[0] = h2f(row[t]);          e[1] = h2f(row[t + 2048]);
    e[2] = h2f(row[t + 1024]);   e[3] = h2f(row[t + 3072]);
    e[4] = h2f(row[t + 512]);    e[5] = h2f(row[t + 2560]);
    e[6] = h2f(row[t + 1536]);   e[7] = h2f(row[t + 3584]);
    radix8(e, ONE, ONE, ONE);
#pragma unroll
    for (int j = 0; j < 8; j++) xs[XPAD(8 * g + j)] = e[j];
    __syncthreads();

    fpass<4>(xs, g_TW, t, 1024);
    __syncthreads();
    fpass<6>(xs, g_TW, t, 1024);
    __syncthreads();
    fpass<8>(xs, g_TW, t, 1024);
    __syncthreads();

    float2 f[8];
#pragma unroll
    for (int j = 0; j < 8; j++) f[j] = xs[XPAD(t + 512 * j)];
    radix8(f, ldtw(g_TW + 512 + t), ldtw(g_TW + 1024 + t), ldtw(g_TW + 2048 + t));
    __half2* out = g_U + (size_t)col * 4096;
    const float sc = 0.015625f;
#pragma unroll
    for (int j = 0; j < 8; j++)
        out[t + 512 * j] = f2h(make_float2(f[j].x * sc, f[j].y * sc));
}

// ---------------------------------------------------------------------------
// K3: transpose back  H[p][k] = U[k][p]
// ---------------------------------------------------------------------------
__global__ void kern_trback() {
    __shared__ __half2 tile[32][33];
    const int p0 = blockIdx.x * 32, k0 = blockIdx.y * 32;
    const int tx = threadIdx.x, ty = threadIdx.y;
    const __half2 Z = __floats2half2_rn(0.f, 0.f);
#pragma unroll
    for (int j = 0; j < 32; j += 8) {
        int k = k0 + ty + j;
        tile[ty + j][tx] = (k <= M_HALF) ? g_U[(size_t)k * 4096 + p0 + tx] : Z;
    }
    __syncthreads();
#pragma unroll
    for (int j = 0; j < 32; j += 8) {
        int k = k0 + tx;
        if (k <= M_HALF)
            g_H[(size_t)(p0 + ty + j) * HSTR + k] = tile[tx][ty + j];
    }
}

// ---------------------------------------------------------------------------
// K4: per row o: half-spectrum irfft, fp16 out. Final scale 2^-18.
// ---------------------------------------------------------------------------
#define IRFFT_SMEM (2052 * 4 + 2184 * 8)
__global__ __launch_bounds__(512) void kern_irfft() {
    extern __shared__ char dyn1[];
    __half2* hbuf = (__half2*)dyn1;
    float2*  xs   = (float2*)(dyn1 + 2052 * 4);
    const int t = threadIdx.x;
    const int o = blockIdx.x;
    const float2 ONE = make_float2(1.f, 0.f);

    const __half2* hrow = g_H + (size_t)o * HSTR;
    for (int k = t; k < 2049; k += 512) hbuf[k] = hrow[k];
    __syncthreads();

    if (t < 256) {
        const int g = __brev((unsigned)t) >> 24;
        const int B3[8] = {0, 4, 2, 6, 1, 5, 3, 7};
        float2 e[8];
#pragma unroll
        for (int j = 0; j < 8; j++) {
            int kk = t + 256 * B3[j];
            float2 Hk, Ck;
            if (kk == 0) {
                Hk = make_float2(h2f(hbuf[0]).x, 0.f);
                Ck = make_float2(h2f(hbuf[M_HALF]).x, 0.f);
            } else {
                Hk = h2f(hbuf[kk]);
                float2 c = h2f(hbuf[M_HALF - kk]);
                Ck = make_float2(c.x, -c.y);
            }
            float2 S = cadd(Hk, Ck);
            float2 D = csub(Hk, Ck);
            e[j] = cadd(S, rot90(cmul(D, ldtw(g_TW + 2048 + kk))));
        }
        radix8(e, ONE, ONE, ONE);
#pragma unroll
        for (int j = 0; j < 8; j++) xs[XPAD(8 * g + j)] = e[j];
    }
    __syncthreads();

    fpass<4>(xs, g_TW, t, 512);
    __syncthreads();
    fpass<6>(xs, g_TW, t, 512);
    __syncthreads();
    for (int u = t; u < 1024; u += 512) {
        int kk = u & 127;
        int i0 = ((u >> 7) << 8) + kk;
        int ia = XPAD(i0), ib = XPAD(i0 + 128);
        float2 w = ldtw(g_TW + 128 + kk);
        float2 uu = xs[ia], v = cmul(xs[ib], w);
        xs[ia] = cadd(uu, v);
        xs[ib] = csub(uu, v);
    }
    __syncthreads();

    if (t < 256) {
        float2 f[8];
#pragma unroll
        for (int j = 0; j < 8; j++) f[j] = xs[XPAD(t + 256 * j)];
        radix8(f, ldtw(g_TW + 256 + t), ldtw(g_TW + 512 + t), ldtw(g_TW + 1024 + t));
        const float s = 1.0f / 262144.0f;   // 2^-18
        __half* rowB = g_Bp + (size_t)o * KEXP;
#pragma unroll
        for (int j = 0; j < 8; j++) {
            int m = t + 256 * j;
            __half2 hp;
            hp.x = __float2half(f[j].x * s);
            hp.y = __float2half(f[j].y * s);
            *(__half2*)(rowB + 2 * m) = hp;
        }
    }
}

// ---------------------------------------------------------------------------
// mma.sync GEMM: CTA 64x128, 4 warps (2Mx2N), warp tile 32x64, BK=64,
// 3-stage cp.async (72KB -> 3 CTAs/SM), prefetch-first single barrier.
// ---------------------------------------------------------------------------
#define GM 64
#define GN 128
#define TILE_K 64
#define STAGES 3
#define A_ST (GM * 128)                   // 8KB
#define B_ST (GN * 128)                   // 16KB
#define STAGE_BYTES (A_ST + B_ST)         // 24KB
#define NT (KEXP / TILE_K)                // 64
#define GEMM_SMEM (STAGES * STAGE_BYTES)  // 72KB

__global__ __launch_bounds__(128, 3) void kern_gemm_mma(const float* __restrict__ bias,
                                                        float* __restrict__ C) {
    extern __shared__ char dsm[];
    const uint32_t smem = smem_u32(dsm);
    const int tid  = threadIdx.x;
    const int wid  = tid >> 5;
    const int lane = tid & 31;
    const int m0   = (wid & 1) * 32;
    const int n0   = (wid >> 1) * 64;

    const __half* gA = g_Ap + (size_t)(blockIdx.y * GM) * KEXP;
    const __half* gB = g_Bp + (size_t)(blockIdx.x * GN) * KEXP;

    const int crow = tid >> 3;
    const int ccol = tid & 7;

    auto load_tile = [&](int t, int s) {
        const uint32_t sA = smem + s * STAGE_BYTES;
        const uint32_t sB = sA + A_ST;
        const char* srcA = (const char*)(gA + (size_t)t * TILE_K);
        const char* srcB = (const char*)(gB + (size_t)t * TILE_K);
#pragma unroll
        for (int r = 0; r < 4; r++) {
            int row = crow + r * 16;
            CP16(sA + swz(row, ccol * 16), srcA + (size_t)row * (KEXP * 2) + ccol * 16);
        }
#pragma unroll
        for (int r = 0; r < 8; r++) {
            int row = crow + r * 16;
            CP16(sB + swz(row, ccol * 16), srcB + (size_t)row * (KEXP * 2) + ccol * 16);
        }
    };

    float acc[2][8][4];
#pragma unroll
    for (int mt = 0; mt < 2; mt++)
#pragma unroll
        for (int nt = 0; nt < 8; nt++)
#pragma unroll
            for (int j = 0; j < 4; j++) acc[mt][nt][j] = 0.f;

    const int l7 = lane & 7;
    const int a_row = m0 + ((lane >> 3) & 1) * 8 + l7;
    const int a_kb  = ((lane >> 4) & 1) * 16;
    const int b_row = n0 + ((lane >> 4) & 1) * 8 + l7;
    const int b_kb  = ((lane >> 3) & 1) * 16;

    load_tile(0, 0); CP_COMMIT();
    load_tile(1, 1); CP_COMMIT();

#pragma unroll 1
    for (int t = 0; t < NT; t++) {
        asm volatile("cp.async.wait_group 1;" ::: "memory");
        __syncthreads();

        const int tn = t + 2;
        if (tn < NT) load_tile(tn, tn % STAGES);
        CP_COMMIT();

        const int s = t % STAGES;
        const uint32_t sA = smem + s * STAGE_BYTES;
        const uint32_t sB = sA + A_ST;

#pragma unroll
        for (int ks = 0; ks < 4; ks++) {
            const int kb = ks * 32;
            uint32_t a[2][4], b[8][2];
#pragma unroll
            for (int mt = 0; mt < 2; mt++) {
                uint32_t addr = sA + swz(a_row + mt * 16, kb + a_kb);
                LDSM_X4(a[mt][0], a[mt][1], a[mt][2], a[mt][3], addr);
            }
#pragma unroll
            for (int bt = 0; bt < 4; bt++) {
                uint32_t addr = sB + swz(b_row + bt * 16, kb + b_kb);
                LDSM_X4(b[2 * bt][0], b[2 * bt][1], b[2 * bt + 1][0], b[2 * bt + 1][1], addr);
            }
#pragma unroll
            for (int mt = 0; mt < 2; mt++)
#pragma unroll
                for (int nt = 0; nt < 8; nt++)
                    MMA16816(acc[mt][nt], a[mt], b[nt]);
        }
    }

    const int gid = lane >> 2;
    const int tig = lane & 3;
    float bv[8][2];
#pragma unroll
    for (int nt = 0; nt < 8; nt++) {
        const int col = blockIdx.x * GN + n0 + nt * 8 + 2 * tig;
        bv[nt][0] = __ldg(bias + col);
        bv[nt][1] = __ldg(bias + col + 1);
    }
#pragma unroll
    for (int mt = 0; mt < 2; mt++) {
        const int row0 = blockIdx.y * GM + m0 + mt * 16 + gid;
#pragma unroll
        for (int nt = 0; nt < 8; nt++) {
            const int col = blockIdx.x * GN + n0 + nt * 8 + 2 * tig;
            *(float2*)(C + (size_t)row0 * O_SZ + col) =
                make_float2(acc[mt][nt][0] + bv[nt][0], acc[mt][nt][1] + bv[nt][1]);
            *(float2*)(C + (size_t)(row0 + 8) * O_SZ + col) =
                make_float2(acc[mt][nt][2] + bv[nt][0], acc[mt][nt][3] + bv[nt][1]);
        }
    }
}

// ---------------------------------------------------------------------------
// Launch
// ---------------------------------------------------------------------------
extern "C" void kernel_launch(void* const* d_in, const int* in_sizes, int n_in,
                              void* d_out, int out_size) {
    const float* data = (const float*)d_in[0];
    const float* wr   = (const float*)d_in[1];
    const float* wi   = (const float*)d_in[2];
    const float* bias = (const float*)d_in[3];
    const int*   zmat = (const int*)d_in[4];
    float*       out  = (float*)d_out;

    cudaFuncSetAttribute(kern_gemm_mma, cudaFuncAttributeMaxDynamicSharedMemorySize, GEMM_SMEM);
    cudaFuncSetAttribute(kern_fft0,     cudaFuncAttributeMaxDynamicSharedMemorySize, FFT0_SMEM);
    cudaFuncSetAttribute(kern_irfft,    cudaFuncAttributeMaxDynamicSharedMemorySize, IRFFT_SMEM);

    kern_mtrans<<<dim3(4096 / 32, 130), dim3(32, 8)>>>(wr, wi, zmat, data);
    kern_fft0<<<2049, 512, FFT0_SMEM>>>();
    kern_trback<<<dim3(4096 / 32, 65), dim3(32, 8)>>>();
    kern_irfft<<<O_SZ, 512, IRFFT_SMEM>>>();
    kern_gemm_mma<<<dim3(O_SZ / GN, B_SZ / GM), 128, GEMM_SMEM>>>(bias, out);
}